// round 5
// baseline (speedup 1.0000x reference)
#include <cuda_runtime.h>
#include <math.h>

#define E_DIM 1024
#define S_LEN 2048
#define NHEAD 16

// ---------------- scratch (no allocation allowed) ----------------
__device__ float g_qkv[25165824];   // 8192 x 3072
__device__ float g_q2 [8388608];    // 8192 x 1024  (B,S,H,D)
__device__ float g_k2 [8388608];
__device__ float g_v2 [8388608];
__device__ float g_ctx[8388608];    // (B,S,H,D)

// ---------------- SGEMM: C[M,N] = A[M,K] @ B[N,K]^T + bias[N] ----------------
#define BM 128
#define BN 128
#define BK 16

__global__ __launch_bounds__(256, 2)
void sgemm_nt(const float* __restrict__ A, int lda,
              const float* __restrict__ B, int ldb,
              const float* __restrict__ bias,
              float* __restrict__ C, int ldc, int K)
{
    __shared__ float As[BK][BM];
    __shared__ float Bs[BK][BN];

    const int tid = threadIdx.x;
    const int tx = tid & 15;
    const int ty = tid >> 4;

    const float* Ab = A + (size_t)blockIdx.y * BM * lda;
    const float* Bb = B + (size_t)blockIdx.x * BN * ldb;

    const int lr = tid >> 2;            // 0..63
    const int lc = (tid & 3) << 2;      // 0,4,8,12

    float acc[8][8];
#pragma unroll
    for (int j = 0; j < 8; j++)
#pragma unroll
        for (int i = 0; i < 8; i++) acc[j][i] = 0.0f;

    float4 a0 = *(const float4*)(Ab + (size_t)lr * lda + lc);
    float4 a1 = *(const float4*)(Ab + (size_t)(lr + 64) * lda + lc);
    float4 b0 = *(const float4*)(Bb + (size_t)lr * ldb + lc);
    float4 b1 = *(const float4*)(Bb + (size_t)(lr + 64) * ldb + lc);

    for (int k0 = 0; k0 < K; k0 += BK) {
        As[lc + 0][lr]      = a0.x; As[lc + 1][lr]      = a0.y;
        As[lc + 2][lr]      = a0.z; As[lc + 3][lr]      = a0.w;
        As[lc + 0][lr + 64] = a1.x; As[lc + 1][lr + 64] = a1.y;
        As[lc + 2][lr + 64] = a1.z; As[lc + 3][lr + 64] = a1.w;
        Bs[lc + 0][lr]      = b0.x; Bs[lc + 1][lr]      = b0.y;
        Bs[lc + 2][lr]      = b0.z; Bs[lc + 3][lr]      = b0.w;
        Bs[lc + 0][lr + 64] = b1.x; Bs[lc + 1][lr + 64] = b1.y;
        Bs[lc + 2][lr + 64] = b1.z; Bs[lc + 3][lr + 64] = b1.w;
        __syncthreads();

        if (k0 + BK < K) {
            const float* Ap = Ab + (k0 + BK);
            const float* Bp = Bb + (k0 + BK);
            a0 = *(const float4*)(Ap + (size_t)lr * lda + lc);
            a1 = *(const float4*)(Ap + (size_t)(lr + 64) * lda + lc);
            b0 = *(const float4*)(Bp + (size_t)lr * ldb + lc);
            b1 = *(const float4*)(Bp + (size_t)(lr + 64) * ldb + lc);
        }

#pragma unroll 8
        for (int k = 0; k < BK; k++) {
            float ar[8], br[8];
            float4 t;
            t = *(const float4*)&As[k][ty << 2];
            ar[0] = t.x; ar[1] = t.y; ar[2] = t.z; ar[3] = t.w;
            t = *(const float4*)&As[k][64 + (ty << 2)];
            ar[4] = t.x; ar[5] = t.y; ar[6] = t.z; ar[7] = t.w;
            t = *(const float4*)&Bs[k][tx << 2];
            br[0] = t.x; br[1] = t.y; br[2] = t.z; br[3] = t.w;
            t = *(const float4*)&Bs[k][64 + (tx << 2)];
            br[4] = t.x; br[5] = t.y; br[6] = t.z; br[7] = t.w;
#pragma unroll
            for (int j = 0; j < 8; j++)
#pragma unroll
                for (int i = 0; i < 8; i++)
                    acc[j][i] += ar[j] * br[i];
        }
        __syncthreads();
    }

    const int cb0 = blockIdx.x * BN + (tx << 2);
    float4 bi0 = *(const float4*)(bias + cb0);
    float4 bi1 = *(const float4*)(bias + cb0 + 64);
    const size_t rbase = (size_t)blockIdx.y * BM;
#pragma unroll
    for (int j = 0; j < 8; j++) {
        int rr = (j < 4) ? ((ty << 2) + j) : (64 + (ty << 2) + (j - 4));
        float* Cp = C + (rbase + rr) * (size_t)ldc + cb0;
        float4 v0 = make_float4(acc[j][0] + bi0.x, acc[j][1] + bi0.y,
                                acc[j][2] + bi0.z, acc[j][3] + bi0.w);
        float4 v1 = make_float4(acc[j][4] + bi1.x, acc[j][5] + bi1.y,
                                acc[j][6] + bi1.z, acc[j][7] + bi1.w);
        *(float4*)Cp = v0;
        *(float4*)(Cp + 64) = v1;
    }
}

// ---------------- RoPE on q,k segments of qkv (in place) ----------------
// qkv row m = b*S + s, cols: [0,1024) q, [1024,2048) k.
// out[i]    = t[i]*cos - t[i+32]*sin ; out[i+32] = t[i+32]*cos + t[i]*sin
__global__ void rope_kernel(float* __restrict__ qkv)
{
    int idx = blockIdx.x * 256 + threadIdx.x;     // 8192 * 16 * 32 threads
    int i = idx & 31;
    int h = (idx >> 5) & 15;
    int m = idx >> 9;
    int s = m & (S_LEN - 1);
    // inv_freq = 10000^(-i/32); compute in double to land within 1 ulp of fp32 truth
    float inv = (float)exp2(-(double)i * 0.41524101186091903); // log2(10000)/32
    float ang = (float)s * inv;
    float c, sn;
    sincosf(ang, &sn, &c);
    size_t base = (size_t)m * 3072 + (h << 6) + i;
    float q0 = qkv[base], q1 = qkv[base + 32];
    qkv[base]        = q0 * c - q1 * sn;
    qkv[base + 32]   = q1 * c + q0 * sn;
    float k0 = qkv[base + 1024], k1 = qkv[base + 1056];
    qkv[base + 1024] = k0 * c - k1 * sn;
    qkv[base + 1056] = k1 * c + k0 * sn;
}

// ---------------- Flash attention, fp32, Br=Bc=64, D=64 ----------------
#define ASD 68                                        // padded smem row stride
#define ATTN_SMEM (4 * 64 * ASD * 4 + 2048)           // Qs,Ks,Vs,Ps + mask bytes

__global__ __launch_bounds__(256, 2)
void attn_kernel(const float* __restrict__ Qg, const float* __restrict__ Kg,
                 const float* __restrict__ Vg, const unsigned char* __restrict__ maskg,
                 float* __restrict__ Og)
{
    extern __shared__ float smem[];
    float* Qs = smem;
    float* Ks = Qs + 64 * ASD;
    float* Vs = Ks + 64 * ASD;
    float* Ps = Vs + 64 * ASD;
    unsigned char* Ms = (unsigned char*)(Ps + 64 * ASD);

    const int b = blockIdx.z, h = blockIdx.y;
    const int q0 = blockIdx.x << 6;
    const int tid = threadIdx.x;
    const int tx = tid & 15, ty = tid >> 4;

    const size_t bh = (size_t)b * S_LEN * E_DIM + (h << 6);
    const float* Qb = Qg + bh + (size_t)q0 * E_DIM;
    const float* Kb = Kg + bh;
    const float* Vb = Vg + bh;

    // load Q tile (row-major [r][d], padded) + this batch's mask row
#pragma unroll
    for (int t = 0; t < 4; t++) {
        int idx = tid + t * 256;
        int r = idx >> 4, d4 = (idx & 15) << 2;
        *(float4*)&Qs[r * ASD + d4] = *(const float4*)(Qb + (size_t)r * E_DIM + d4);
    }
    {
        const unsigned int* mw = (const unsigned int*)(maskg + (size_t)b * S_LEN);
        unsigned int* msw = (unsigned int*)Ms;
        msw[tid] = mw[tid];
        msw[tid + 256] = mw[tid + 256];
    }

    float mrow[4], lrow[4], o[4][4];
#pragma unroll
    for (int j = 0; j < 4; j++) {
        mrow[j] = -1e30f; lrow[j] = 0.0f;
#pragma unroll
        for (int i = 0; i < 4; i++) o[j][i] = 0.0f;
    }

    for (int kt = 0; kt < 32; kt++) {
        const int kb = kt << 6;
        __syncthreads();   // prev O-phase done; also covers Q/mask load at kt=0
#pragma unroll
        for (int t = 0; t < 4; t++) {
            int idx = tid + t * 256;
            int r = idx >> 4, d4 = (idx & 15) << 2;
            *(float4*)&Ks[r * ASD + d4] = *(const float4*)(Kb + (size_t)(kb + r) * E_DIM + d4);
            *(float4*)&Vs[r * ASD + d4] = *(const float4*)(Vb + (size_t)(kb + r) * E_DIM + d4);
        }
        __syncthreads();

        // S = Q K^T : thread rows 4ty..+3 (contig), cols tx+16i (strided, bank-clean)
        float s[4][4];
#pragma unroll
        for (int j = 0; j < 4; j++)
#pragma unroll
            for (int i = 0; i < 4; i++) s[j][i] = 0.0f;

#pragma unroll 4
        for (int d4 = 0; d4 < 64; d4 += 4) {
            float qq[4][4], kk[4][4];
#pragma unroll
            for (int j = 0; j < 4; j++) {
                float4 t = *(const float4*)&Qs[(4 * ty + j) * ASD + d4];
                qq[j][0] = t.x; qq[j][1] = t.y; qq[j][2] = t.z; qq[j][3] = t.w;
            }
#pragma unroll
            for (int i = 0; i < 4; i++) {
                float4 t = *(const float4*)&Ks[(tx + 16 * i) * ASD + d4];
                kk[i][0] = t.x; kk[i][1] = t.y; kk[i][2] = t.z; kk[i][3] = t.w;
            }
#pragma unroll
            for (int j = 0; j < 4; j++)
#pragma unroll
                for (int i = 0; i < 4; i++)
#pragma unroll
                    for (int dd = 0; dd < 4; dd++)
                        s[j][i] += qq[j][dd] * kk[i][dd];
        }

        bool msk[4];
#pragma unroll
        for (int i = 0; i < 4; i++) msk[i] = Ms[kb + tx + 16 * i] != 0;

        // online softmax (16-lane shuffle groups share a row)
#pragma unroll
        for (int j = 0; j < 4; j++) {
#pragma unroll
            for (int i = 0; i < 4; i++)
                s[j][i] = msk[i] ? -1e30f : s[j][i] * 0.125f;
            float tm = fmaxf(fmaxf(s[j][0], s[j][1]), fmaxf(s[j][2], s[j][3]));
#pragma unroll
            for (int off = 8; off > 0; off >>= 1)
                tm = fmaxf(tm, __shfl_xor_sync(0xffffffffu, tm, off));
            float mn = fmaxf(mrow[j], tm);
            float corr = __expf(mrow[j] - mn);
            mrow[j] = mn;
            float rs = 0.0f;
#pragma unroll
            for (int i = 0; i < 4; i++) { s[j][i] = __expf(s[j][i] - mn); rs += s[j][i]; }
#pragma unroll
            for (int off = 8; off > 0; off >>= 1)
                rs += __shfl_xor_sync(0xffffffffu, rs, off);
            lrow[j] = lrow[j] * corr + rs;
#pragma unroll
            for (int i = 0; i < 4; i++) o[j][i] *= corr;
        }

        // stage P (scalar stores, conflict-free by construction)
#pragma unroll
        for (int j = 0; j < 4; j++)
#pragma unroll
            for (int i = 0; i < 4; i++)
                Ps[(4 * ty + j) * ASD + tx + 16 * i] = s[j][i];
        __syncthreads();

        // O += P @ V : thread rows 4ty..+3, dims 4tx..+3
#pragma unroll 4
        for (int cb = 0; cb < 16; cb++) {
            float pp[4][4], vv[4][4];
#pragma unroll
            for (int j = 0; j < 4; j++) {
                float4 t = *(const float4*)&Ps[(4 * ty + j) * ASD + (cb << 2)];
                pp[j][0] = t.x; pp[j][1] = t.y; pp[j][2] = t.z; pp[j][3] = t.w;
            }
#pragma unroll
            for (int cc = 0; cc < 4; cc++) {
                float4 t = *(const float4*)&Vs[((cb << 2) + cc) * ASD + (tx << 2)];
                vv[cc][0] = t.x; vv[cc][1] = t.y; vv[cc][2] = t.z; vv[cc][3] = t.w;
            }
#pragma unroll
            for (int j = 0; j < 4; j++)
#pragma unroll
                for (int cc = 0; cc < 4; cc++)
#pragma unroll
                    for (int i = 0; i < 4; i++)
                        o[j][i] += pp[j][cc] * vv[cc][i];
        }
    }

    float* Ob = Og + bh + (size_t)q0 * E_DIM;
#pragma unroll
    for (int j = 0; j < 4; j++) {
        float inv = 1.0f / lrow[j];
        float4 r = make_float4(o[j][0] * inv, o[j][1] * inv, o[j][2] * inv, o[j][3] * inv);
        *(float4*)(Ob + (size_t)(4 * ty + j) * E_DIM + (tx << 2)) = r;
    }
}

// ---------------- launch ----------------
extern "C" void kernel_launch(void* const* d_in, const int* in_sizes, int n_in,
                              void* d_out, int out_size)
{
    const float* x     = (const float*)d_in[0];
    const float* w_in  = (const float*)d_in[1];   // (3072,1024)
    const float* b_in  = (const float*)d_in[2];   // (3072,)
    const float* w_out = (const float*)d_in[3];   // (1024,1024)
    const float* b_out = (const float*)d_in[4];   // (1024,)
    const unsigned char* mask = (const unsigned char*)d_in[5]; // (4,2048) bool
    float* out = (float*)d_out;

    float *qkv, *q2, *k2, *v2, *ctx;
    cudaGetSymbolAddress((void**)&qkv, g_qkv);
    cudaGetSymbolAddress((void**)&q2,  g_q2);
    cudaGetSymbolAddress((void**)&k2,  g_k2);
    cudaGetSymbolAddress((void**)&v2,  g_v2);
    cudaGetSymbolAddress((void**)&ctx, g_ctx);

    cudaFuncSetAttribute(attn_kernel, cudaFuncAttributeMaxDynamicSharedMemorySize, ATTN_SMEM);

    // 1) combined = x @ Win^T + b          (8192 x 3072)
    sgemm_nt<<<dim3(24, 64), 256>>>(x, 1024, w_in, 1024, b_in, qkv, 3072, 1024);
    // 2) RoPE on q,k in place
    rope_kernel<<<16384, 256>>>(qkv);
    // 3) redundant second projection q2/k2/v2 (each 8192 x 1024)
    sgemm_nt<<<dim3(8, 64), 256>>>(qkv,        3072, w_in,               1024, b_in,        q2, 1024, 1024);
    sgemm_nt<<<dim3(8, 64), 256>>>(qkv + 1024, 3072, w_in + 1024 * 1024, 1024, b_in + 1024, k2, 1024, 1024);
    sgemm_nt<<<dim3(8, 64), 256>>>(qkv + 2048, 3072, w_in + 2048 * 1024, 1024, b_in + 2048, v2, 1024, 1024);
    // 4) attention -> ctx in (B,S,H,D)
    attn_kernel<<<dim3(32, 16, 4), 256, ATTN_SMEM>>>(q2, k2, v2, mask, ctx);
    // 5) out = ctx @ Wout^T + b
    sgemm_nt<<<dim3(8, 64), 256>>>(ctx, 1024, w_out, 1024, b_out, out, 1024, 1024);
}

// round 7
// speedup vs baseline: 1.6063x; 1.6063x over previous
#include <cuda_runtime.h>
#include <cuda_bf16.h>
#include <math.h>
#include <stdint.h>

#define E_DIM 1024
#define S_LEN 2048

// ---------------- scratch (no allocation allowed) ----------------
__device__ float g_qkv[25165824];   // 8192 x 3072 fp32
__device__ float g_q2 [8388608];    // 8192 x 1024 fp32
__device__ float g_k2 [8388608];
__device__ float g_v2 [8388608];
__device__ float g_ctx[8388608];

__device__ __nv_bfloat16 g_xh [8388608],  g_xl [8388608];    // x split
__device__ __nv_bfloat16 g_wih[3145728],  g_wil[3145728];    // w_in split
__device__ __nv_bfloat16 g_woh[1048576],  g_wol[1048576];    // w_out split
__device__ __nv_bfloat16 g_qkh[25165824], g_qkl[25165824];   // qkv split (post-rope)
__device__ __nv_bfloat16 g_cth[8388608],  g_ctl[8388608];    // ctx split

// ---------------- helpers ----------------
__device__ __forceinline__ uint32_t smem_u32(const void* p) {
    uint32_t a;
    asm("{ .reg .u64 t; cvta.to.shared.u64 t, %1; cvt.u32.u64 %0, t; }" : "=r"(a) : "l"(p));
    return a;
}
__device__ __forceinline__ void cp16(uint32_t s, const void* g) {
    asm volatile("cp.async.cg.shared.global [%0], [%1], 16;" :: "r"(s), "l"(g));
}
__device__ __forceinline__ void ldsm4(uint32_t* r, uint32_t a) {
    asm volatile("ldmatrix.sync.aligned.m8n8.x4.shared.b16 {%0,%1,%2,%3}, [%4];"
        : "=r"(r[0]), "=r"(r[1]), "=r"(r[2]), "=r"(r[3]) : "r"(a));
}
__device__ __forceinline__ void mma_bf16(float* c, const uint32_t* a, const uint32_t* b) {
    asm volatile("mma.sync.aligned.m16n8k16.row.col.f32.bf16.bf16.f32 "
        "{%0,%1,%2,%3}, {%4,%5,%6,%7}, {%8,%9}, {%0,%1,%2,%3};"
        : "+f"(c[0]), "+f"(c[1]), "+f"(c[2]), "+f"(c[3])
        : "r"(a[0]), "r"(a[1]), "r"(a[2]), "r"(a[3]), "r"(b[0]), "r"(b[1]));
}

// ---------------- split fp32 -> bf16 hi + bf16 lo ----------------
__global__ void split_kernel(const float* __restrict__ src,
                             __nv_bfloat16* __restrict__ hi,
                             __nv_bfloat16* __restrict__ lo, int n4)
{
    int q = blockIdx.x * 256 + threadIdx.x;
    if (q >= n4) return;
    int i = q << 2;
    float4 v = *(const float4*)(src + i);
    float f[4] = {v.x, v.y, v.z, v.w};
    __nv_bfloat16 h[4], l[4];
#pragma unroll
    for (int j = 0; j < 4; j++) {
        h[j] = __float2bfloat16_rn(f[j]);
        l[j] = __float2bfloat16_rn(f[j] - __bfloat162float(h[j]));
    }
    *(__nv_bfloat162*)(hi + i)     = __nv_bfloat162(h[0], h[1]);
    *(__nv_bfloat162*)(hi + i + 2) = __nv_bfloat162(h[2], h[3]);
    *(__nv_bfloat162*)(lo + i)     = __nv_bfloat162(l[0], l[1]);
    *(__nv_bfloat162*)(lo + i + 2) = __nv_bfloat162(l[2], l[3]);
}

// ---------------- mma.sync bf16x2 GEMM: C[M,N] = A[M,K] @ B[N,K]^T + bias ----------------
// CTA tile 128x128, K-block 32 bf16, 3-stage cp.async pipeline, swizzled smem.
#define OPB       8192                 // one operand tile: 128 rows x 64B
#define STGB      (4 * OPB)            // Ah, Al, Bh, Bl
#define GEMM_SMEM (3 * STGB)           // 98304 B

__device__ __forceinline__ void issue_stage(uint32_t sb, int stg, int k0,
    const __nv_bfloat16* Ahb, const __nv_bfloat16* Alb,
    const __nv_bfloat16* Bhb, const __nv_bfloat16* Blb,
    int lda, int ldb, int lr, int lr1, int lkc, uint32_t so0, uint32_t so1)
{
    uint32_t s = sb + (uint32_t)stg * STGB;
    const int kb8 = k0 + lkc * 8;
    cp16(s +           so0, Ahb + (size_t)lr  * lda + kb8);
    cp16(s +           so1, Ahb + (size_t)lr1 * lda + kb8);
    cp16(s + OPB +     so0, Alb + (size_t)lr  * lda + kb8);
    cp16(s + OPB +     so1, Alb + (size_t)lr1 * lda + kb8);
    cp16(s + 2 * OPB + so0, Bhb + (size_t)lr  * ldb + kb8);
    cp16(s + 2 * OPB + so1, Bhb + (size_t)lr1 * ldb + kb8);
    cp16(s + 3 * OPB + so0, Blb + (size_t)lr  * ldb + kb8);
    cp16(s + 3 * OPB + so1, Blb + (size_t)lr1 * ldb + kb8);
    asm volatile("cp.async.commit_group;" ::: "memory");
}

__global__ __launch_bounds__(256, 1)
void gemm_mma(const __nv_bfloat16* __restrict__ Ah, const __nv_bfloat16* __restrict__ Al, int lda,
              const __nv_bfloat16* __restrict__ Bh, const __nv_bfloat16* __restrict__ Bl, int ldb,
              const float* __restrict__ bias, float* __restrict__ C, int ldc, int K)
{
    extern __shared__ char smraw[];
    const uint32_t sb = smem_u32(smraw);
    const int tid = threadIdx.x;
    const int l = tid & 31, w = tid >> 5;
    const int wm = (w >> 2) * 64, wn = (w & 3) * 32;
    const int mb = blockIdx.y * 128, nb = blockIdx.x * 128;

    const __nv_bfloat16* Ahb = Ah + (size_t)mb * lda;
    const __nv_bfloat16* Alb = Al + (size_t)mb * lda;
    const __nv_bfloat16* Bhb = Bh + (size_t)nb * ldb;
    const __nv_bfloat16* Blb = Bl + (size_t)nb * ldb;

    // loader lane mapping (2 chunks x 4 operands per thread per stage)
    const int lr  = tid >> 2;                                 // rows 0..63
    const int lr1 = lr + 64;
    const int lkc = tid & 3;                                  // 16B chunk in row
    const uint32_t so0 = (uint32_t)(lr  * 64 + ((lkc ^ ((lr  >> 1) & 3)) << 4));
    const uint32_t so1 = (uint32_t)(lr1 * 64 + ((lkc ^ ((lr1 >> 1) & 3)) << 4));

    // ldmatrix lane constants (swizzle-folded; tile bases are multiples of 16 rows)
    const int rA = l & 15, kselA = l >> 4, swA = (rA >> 1) & 3;
    const uint32_t aRow = (uint32_t)((wm + rA) * 64);
    const uint32_t aK0 = (uint32_t)(((0 + kselA) ^ swA) << 4);
    const uint32_t aK1 = (uint32_t)(((2 + kselA) ^ swA) << 4);
    const int rB = (l & 7) + ((l >> 4) << 3), kselB = (l >> 3) & 1, swB = (rB >> 1) & 3;
    const uint32_t bRow = (uint32_t)((wn + rB) * 64);
    const uint32_t bK0 = (uint32_t)(((0 + kselB) ^ swB) << 4);
    const uint32_t bK1 = (uint32_t)(((2 + kselB) ^ swB) << 4);

    float acc[4][4][4];
#pragma unroll
    for (int mi = 0; mi < 4; mi++)
#pragma unroll
        for (int ni = 0; ni < 4; ni++)
#pragma unroll
            for (int i = 0; i < 4; i++) acc[mi][ni][i] = 0.0f;

    const int NKB = K >> 5;
    issue_stage(sb, 0, 0,  Ahb, Alb, Bhb, Blb, lda, ldb, lr, lr1, lkc, so0, so1);
    issue_stage(sb, 1, 32, Ahb, Alb, Bhb, Blb, lda, ldb, lr, lr1, lkc, so0, so1);

    for (int kb = 0; kb < NKB; kb++) {
        if (kb < NKB - 2) asm volatile("cp.async.wait_group 1;" ::: "memory");
        else              asm volatile("cp.async.wait_group 0;" ::: "memory");
        __syncthreads();
        if (kb + 2 < NKB)
            issue_stage(sb, (kb + 2) % 3, (kb + 2) * 32,
                        Ahb, Alb, Bhb, Blb, lda, ldb, lr, lr1, lkc, so0, so1);

        const uint32_t s = sb + (uint32_t)(kb % 3) * STGB;
#pragma unroll
        for (int kk = 0; kk < 2; kk++) {
            const uint32_t aK = kk ? aK1 : aK0;
            const uint32_t bK = kk ? bK1 : bK0;
            uint32_t ah[4][4], al4[4][4], bh[2][4], bl4[2][4];
#pragma unroll
            for (int mi = 0; mi < 4; mi++) {
                ldsm4(ah[mi],  s +           aRow + mi * 1024 + aK);
                ldsm4(al4[mi], s + OPB +     aRow + mi * 1024 + aK);
            }
#pragma unroll
            for (int g = 0; g < 2; g++) {
                ldsm4(bh[g],  s + 2 * OPB + bRow + g * 1024 + bK);
                ldsm4(bl4[g], s + 3 * OPB + bRow + g * 1024 + bK);
            }
#pragma unroll
            for (int mi = 0; mi < 4; mi++)
#pragma unroll
                for (int ni = 0; ni < 4; ni++) {
                    uint32_t* bhp = &bh[ni >> 1][(ni & 1) * 2];
                    uint32_t* blp = &bl4[ni >> 1][(ni & 1) * 2];
                    mma_bf16(acc[mi][ni], ah[mi],  bhp);   // Ah*Bh
                    mma_bf16(acc[mi][ni], ah[mi],  blp);   // Ah*Bl
                    mma_bf16(acc[mi][ni], al4[mi], bhp);   // Al*Bh
                }
        }
    }

    // epilogue: direct stores + bias
    const int cr = l >> 2, cc2 = (l & 3) * 2;
#pragma unroll
    for (int ni = 0; ni < 4; ni++) {
        const int col = nb + wn + ni * 8 + cc2;
        const float b0 = bias[col], b1 = bias[col + 1];
#pragma unroll
        for (int mi = 0; mi < 4; mi++) {
            const int row = mb + wm + mi * 16 + cr;
            float2 v0 = make_float2(acc[mi][ni][0] + b0, acc[mi][ni][1] + b1);
            float2 v1 = make_float2(acc[mi][ni][2] + b0, acc[mi][ni][3] + b1);
            *(float2*)(C + (size_t)row * ldc + col) = v0;
            *(float2*)(C + (size_t)(row + 8) * ldc + col) = v1;
        }
    }
}

// ---------------- RoPE on q,k segments of qkv (in place) ----------------
__global__ void rope_kernel(float* __restrict__ qkv)
{
    int idx = blockIdx.x * 256 + threadIdx.x;
    int i = idx & 31;
    int h = (idx >> 5) & 15;
    int m = idx >> 9;
    int s = m & (S_LEN - 1);
    float inv = (float)exp2(-(double)i * 0.41524101186091903);
    float ang = (float)s * inv;
    float c, sn;
    sincosf(ang, &sn, &c);
    size_t bse = (size_t)m * 3072 + (h << 6) + i;
    float q0 = qkv[bse], q1 = qkv[bse + 32];
    qkv[bse]        = q0 * c - q1 * sn;
    qkv[bse + 32]   = q1 * c + q0 * sn;
    float k0 = qkv[bse + 1024], k1 = qkv[bse + 1056];
    qkv[bse + 1024] = k0 * c - k1 * sn;
    qkv[bse + 1056] = k1 * c + k0 * sn;
}

// ---------------- Flash attention, fp32, Br=Bc=64, D=64 (R5 proven) ----------------
#define ASD 68
#define ATTN_SMEM (4 * 64 * ASD * 4 + 2048)

__global__ __launch_bounds__(256, 2)
void attn_kernel(const float* __restrict__ Qg, const float* __restrict__ Kg,
                 const float* __restrict__ Vg, const unsigned char* __restrict__ maskg,
                 float* __restrict__ Og)
{
    extern __shared__ float smem[];
    float* Qs = smem;
    float* Ks = Qs + 64 * ASD;
    float* Vs = Ks + 64 * ASD;
    float* Ps = Vs + 64 * ASD;
    unsigned char* Ms = (unsigned char*)(Ps + 64 * ASD);

    const int b = blockIdx.z, h = blockIdx.y;
    const int q0 = blockIdx.x << 6;
    const int tid = threadIdx.x;
    const int tx = tid & 15, ty = tid >> 4;

    const size_t bh = (size_t)b * S_LEN * E_DIM + (h << 6);
    const float* Qb = Qg + bh + (size_t)q0 * E_DIM;
    const float* Kb = Kg + bh;
    const float* Vb = Vg + bh;

#pragma unroll
    for (int t = 0; t < 4; t++) {
        int idx = tid + t * 256;
        int r = idx >> 4, d4 = (idx & 15) << 2;
        *(float4*)&Qs[r * ASD + d4] = *(const float4*)(Qb + (size_t)r * E_DIM + d4);
    }
    {
        const unsigned int* mw = (const unsigned int*)(maskg + (size_t)b * S_LEN);
        unsigned int* msw = (unsigned int*)Ms;
        msw[tid] = mw[tid];
        msw[tid + 256] = mw[tid + 256];
    }

    float mrow[4], lrow[4], o[4][4];
#pragma unroll
    for (int j = 0; j < 4; j++) {
        mrow[j] = -1e30f; lrow[j] = 0.0f;
#pragma unroll
        for (int i = 0; i < 4; i++) o[j][i] = 0.0f;
    }

    for (int kt = 0; kt < 32; kt++) {
        const int kb = kt << 6;
        __syncthreads();
#pragma unroll
        for (int t = 0; t < 4; t++) {
            int idx = tid + t * 256;
            int r = idx >> 4, d4 = (idx & 15) << 2;
            *(float4*)&Ks[r * ASD + d4] = *(const float4*)(Kb + (size_t)(kb + r) * E_DIM + d4);
            *(float4*)&Vs[r * ASD + d4] = *(const float4*)(Vb + (size_t)(kb + r) * E_DIM + d4);
        }
        __syncthreads();

        float s[4][4];
#pragma unroll
        for (int j = 0; j < 4; j++)
#pragma unroll
            for (int i = 0; i < 4; i++) s[j][i] = 0.0f;

#pragma unroll 4
        for (int d4 = 0; d4 < 64; d4 += 4) {
            float qq[4][4], kk[4][4];
#pragma unroll
            for (int j = 0; j < 4; j++) {
                float4 t = *(const float4*)&Qs[(4 * ty + j) * ASD + d4];
                qq[j][0] = t.x; qq[j][1] = t.y; qq[j][2] = t.z; qq[j][3] = t.w;
            }
#pragma unroll
            for (int i = 0; i < 4; i++) {
                float4 t = *(const float4*)&Ks[(tx + 16 * i) * ASD + d4];
                kk[i][0] = t.x; kk[i][1] = t.y; kk[i][2] = t.z; kk[i][3] = t.w;
            }
#pragma unroll
            for (int j = 0; j < 4; j++)
#pragma unroll
                for (int i = 0; i < 4; i++)
#pragma unroll
                    for (int dd = 0; dd < 4; dd++)
                        s[j][i] += qq[j][dd] * kk[i][dd];
        }

        bool msk[4];
#pragma unroll
        for (int i = 0; i < 4; i++) msk[i] = Ms[kb + tx + 16 * i] != 0;

#pragma unroll
        for (int j = 0; j < 4; j++) {
#pragma unroll
            for (int i = 0; i < 4; i++)
                s[j][i] = msk[i] ? -1e30f : s[j][i] * 0.125f;
            float tm = fmaxf(fmaxf(s[j][0], s[j][1]), fmaxf(s[j][2], s[j][3]));
#pragma unroll
            for (int off = 8; off > 0; off >>= 1)
                tm = fmaxf(tm, __shfl_xor_sync(0xffffffffu, tm, off));
            float mn = fmaxf(mrow[j], tm);
            float corr = __expf(mrow[j] - mn);
            mrow[j] = mn;
            float rs = 0.0f;
#pragma unroll
            for (int i = 0; i < 4; i++) { s[j][i] = __expf(s[j][i] - mn); rs += s[j][i]; }
#pragma unroll
            for (int off = 8; off > 0; off >>= 1)
                rs += __shfl_xor_sync(0xffffffffu, rs, off);
            lrow[j] = lrow[j] * corr + rs;
#pragma unroll
            for (int i = 0; i < 4; i++) o[j][i] *= corr;
        }

#pragma unroll
        for (int j = 0; j < 4; j++)
#pragma unroll
            for (int i = 0; i < 4; i++)
                Ps[(4 * ty + j) * ASD + tx + 16 * i] = s[j][i];
        __syncthreads();

#pragma unroll 4
        for (int cb = 0; cb < 16; cb++) {
            float pp[4][4], vv[4][4];
#pragma unroll
            for (int j = 0; j < 4; j++) {
                float4 t = *(const float4*)&Ps[(4 * ty + j) * ASD + (cb << 2)];
                pp[j][0] = t.x; pp[j][1] = t.y; pp[j][2] = t.z; pp[j][3] = t.w;
            }
#pragma unroll
            for (int cc = 0; cc < 4; cc++) {
                float4 t = *(const float4*)&Vs[((cb << 2) + cc) * ASD + (tx << 2)];
                vv[cc][0] = t.x; vv[cc][1] = t.y; vv[cc][2] = t.z; vv[cc][3] = t.w;
            }
#pragma unroll
            for (int j = 0; j < 4; j++)
#pragma unroll
                for (int cc = 0; cc < 4; cc++)
#pragma unroll
                    for (int i = 0; i < 4; i++)
                        o[j][i] += pp[j][cc] * vv[cc][i];
        }
    }

    float* Ob = Og + bh + (size_t)q0 * E_DIM;
#pragma unroll
    for (int j = 0; j < 4; j++) {
        float inv = 1.0f / lrow[j];
        float4 r = make_float4(o[j][0] * inv, o[j][1] * inv, o[j][2] * inv, o[j][3] * inv);
        *(float4*)(Ob + (size_t)(4 * ty + j) * E_DIM + (tx << 2)) = r;
    }
}

// ---------------- launch ----------------
extern "C" void kernel_launch(void* const* d_in, const int* in_sizes, int n_in,
                              void* d_out, int out_size)
{
    const float* x     = (const float*)d_in[0];
    const float* w_in  = (const float*)d_in[1];
    const float* b_in  = (const float*)d_in[2];
    const float* w_out = (const float*)d_in[3];
    const float* b_out = (const float*)d_in[4];
    const unsigned char* mask = (const unsigned char*)d_in[5];
    float* out = (float*)d_out;

    float *qkv, *q2, *k2, *v2, *ctx;
    cudaGetSymbolAddress((void**)&qkv, g_qkv);
    cudaGetSymbolAddress((void**)&q2,  g_q2);
    cudaGetSymbolAddress((void**)&k2,  g_k2);
    cudaGetSymbolAddress((void**)&v2,  g_v2);
    cudaGetSymbolAddress((void**)&ctx, g_ctx);
    __nv_bfloat16 *xh, *xl, *wih, *wil, *woh, *wol, *qkh, *qkl, *cth, *ctl;
    cudaGetSymbolAddress((void**)&xh,  g_xh);  cudaGetSymbolAddress((void**)&xl,  g_xl);
    cudaGetSymbolAddress((void**)&wih, g_wih); cudaGetSymbolAddress((void**)&wil, g_wil);
    cudaGetSymbolAddress((void**)&woh, g_woh); cudaGetSymbolAddress((void**)&wol, g_wol);
    cudaGetSymbolAddress((void**)&qkh, g_qkh); cudaGetSymbolAddress((void**)&qkl, g_qkl);
    cudaGetSymbolAddress((void**)&cth, g_cth); cudaGetSymbolAddress((void**)&ctl, g_ctl);

    cudaFuncSetAttribute(attn_kernel, cudaFuncAttributeMaxDynamicSharedMemorySize, ATTN_SMEM);
    cudaFuncSetAttribute(gemm_mma,    cudaFuncAttributeMaxDynamicSharedMemorySize, GEMM_SMEM);

    // split inputs
    split_kernel<<<8192, 256>>>(x,     xh,  xl,  2097152);
    split_kernel<<<3072, 256>>>(w_in,  wih, wil, 786432);
    split_kernel<<<1024, 256>>>(w_out, woh, wol, 262144);

    // 1) qkv = x @ Win^T + b   (8192 x 3072)
    gemm_mma<<<dim3(24, 64), 256, GEMM_SMEM>>>(xh, xl, 1024, wih, wil, 1024, b_in, qkv, 3072, 1024);
    // 2) RoPE in place, then split qkv
    rope_kernel<<<16384, 256>>>(qkv);
    split_kernel<<<24576, 256>>>(qkv, qkh, qkl, 6291456);
    // 3) redundant second projection q2/k2/v2
    gemm_mma<<<dim3(8, 64), 256, GEMM_SMEM>>>(qkh,        qkl,        3072, wih,               wil,               1024, b_in,        q2, 1024, 1024);
    gemm_mma<<<dim3(8, 64), 256, GEMM_SMEM>>>(qkh + 1024, qkl + 1024, 3072, wih + 1024 * 1024, wil + 1024 * 1024, 1024, b_in + 1024, k2, 1024, 1024);
    gemm_mma<<<dim3(8, 64), 256, GEMM_SMEM>>>(qkh + 2048, qkl + 2048, 3072, wih + 2048 * 1024, wil + 2048 * 1024, 1024, b_in + 2048, v2, 1024, 1024);
    // 4) attention (fp32)
    attn_kernel<<<dim3(32, 16, 4), 256, ATTN_SMEM>>>(q2, k2, v2, mask, ctx);
    // 5) out = ctx @ Wout^T + b
    split_kernel<<<8192, 256>>>(ctx, cth, ctl, 2097152);
    gemm_mma<<<dim3(8, 64), 256, GEMM_SMEM>>>(cth, ctl, 1024, woh, wol, 1024, b_out, out, 1024, 1024);
}

// round 9
// speedup vs baseline: 1.7328x; 1.0787x over previous
#include <cuda_runtime.h>
#include <cuda_bf16.h>
#include <math.h>
#include <stdint.h>

#define E_DIM 1024
#define S_LEN 2048

// ---------------- scratch (no allocation allowed) ----------------
__device__ float g_qkv[25165824];   // 8192 x 3072 fp32
__device__ __nv_bfloat16 g_xh [8388608],  g_xl [8388608];
__device__ __nv_bfloat16 g_wih[3145728],  g_wil[3145728];
__device__ __nv_bfloat16 g_woh[1048576],  g_wol[1048576];
__device__ __nv_bfloat16 g_qkh[25165824], g_qkl[25165824];
__device__ __nv_bfloat16 g_qh [8388608],  g_ql [8388608];   // q2 hi/lo (scaled by 0.125)
__device__ __nv_bfloat16 g_kh [8388608],  g_kl [8388608];
__device__ __nv_bfloat16 g_vh [8388608],  g_vl [8388608];
__device__ __nv_bfloat16 g_cth[8388608],  g_ctl[8388608];   // ctx hi/lo

// ---------------- helpers ----------------
__device__ __forceinline__ uint32_t smem_u32(const void* p) {
    uint32_t a;
    asm("{ .reg .u64 t; cvta.to.shared.u64 t, %1; cvt.u32.u64 %0, t; }" : "=r"(a) : "l"(p));
    return a;
}
__device__ __forceinline__ void cp16(uint32_t s, const void* g) {
    asm volatile("cp.async.cg.shared.global [%0], [%1], 16;" :: "r"(s), "l"(g));
}
__device__ __forceinline__ void ldsm4(uint32_t* r, uint32_t a) {
    asm volatile("ldmatrix.sync.aligned.m8n8.x4.shared.b16 {%0,%1,%2,%3}, [%4];"
        : "=r"(r[0]), "=r"(r[1]), "=r"(r[2]), "=r"(r[3]) : "r"(a));
}
__device__ __forceinline__ void ldsm4t(uint32_t* r, uint32_t a) {
    asm volatile("ldmatrix.sync.aligned.m8n8.x4.trans.shared.b16 {%0,%1,%2,%3}, [%4];"
        : "=r"(r[0]), "=r"(r[1]), "=r"(r[2]), "=r"(r[3]) : "r"(a));
}
__device__ __forceinline__ void mma_bf16(float* c, const uint32_t* a, const uint32_t* b) {
    asm volatile("mma.sync.aligned.m16n8k16.row.col.f32.bf16.bf16.f32 "
        "{%0,%1,%2,%3}, {%4,%5,%6,%7}, {%8,%9}, {%0,%1,%2,%3};"
        : "+f"(c[0]), "+f"(c[1]), "+f"(c[2]), "+f"(c[3])
        : "r"(a[0]), "r"(a[1]), "r"(a[2]), "r"(a[3]), "r"(b[0]), "r"(b[1]));
}
__device__ __forceinline__ uint32_t pack2(__nv_bfloat16 a, __nv_bfloat16 b) {
    unsigned short ua = *(unsigned short*)&a, ub = *(unsigned short*)&b;
    return (uint32_t)ua | ((uint32_t)ub << 16);
}
__device__ __forceinline__ void split2(float x, float y, uint32_t& hi, uint32_t& lo) {
    __nv_bfloat16 hx = __float2bfloat16_rn(x);
    __nv_bfloat16 hy = __float2bfloat16_rn(y);
    __nv_bfloat16 lx = __float2bfloat16_rn(x - __bfloat162float(hx));
    __nv_bfloat16 ly = __float2bfloat16_rn(y - __bfloat162float(hy));
    hi = pack2(hx, hy); lo = pack2(lx, ly);
}

// ---------------- split fp32 -> bf16 hi + bf16 lo ----------------
__global__ void split_kernel(const float* __restrict__ src,
                             __nv_bfloat16* __restrict__ hi,
                             __nv_bfloat16* __restrict__ lo, int n4)
{
    int q = blockIdx.x * 256 + threadIdx.x;
    if (q >= n4) return;
    int i = q << 2;
    float4 v = *(const float4*)(src + i);
    float f[4] = {v.x, v.y, v.z, v.w};
    __nv_bfloat16 h[4], l[4];
#pragma unroll
    for (int j = 0; j < 4; j++) {
        h[j] = __float2bfloat16_rn(f[j]);
        l[j] = __float2bfloat16_rn(f[j] - __bfloat162float(h[j]));
    }
    *(__nv_bfloat162*)(hi + i)     = __nv_bfloat162(h[0], h[1]);
    *(__nv_bfloat162*)(hi + i + 2) = __nv_bfloat162(h[2], h[3]);
    *(__nv_bfloat162*)(lo + i)     = __nv_bfloat162(l[0], l[1]);
    *(__nv_bfloat162*)(lo + i + 2) = __nv_bfloat162(l[2], l[3]);
}

// ---------------- mma.sync bf16x2 GEMM: C[M,N] = A[M,K] @ B[N,K]^T + bias ----------------
#define OPB       8192
#define STGB      (4 * OPB)
#define GEMM_SMEM (3 * STGB)

__device__ __forceinline__ void issue_stage(uint32_t sb, int stg, int k0,
    const __nv_bfloat16* Ahb, const __nv_bfloat16* Alb,
    const __nv_bfloat16* Bhb, const __nv_bfloat16* Blb,
    int lda, int ldb, int lr, int lr1, int lkc, uint32_t so0, uint32_t so1)
{
    uint32_t s = sb + (uint32_t)stg * STGB;
    const int kb8 = k0 + lkc * 8;
    cp16(s +           so0, Ahb + (size_t)lr  * lda + kb8);
    cp16(s +           so1, Ahb + (size_t)lr1 * lda + kb8);
    cp16(s + OPB +     so0, Alb + (size_t)lr  * lda + kb8);
    cp16(s + OPB +     so1, Alb + (size_t)lr1 * lda + kb8);
    cp16(s + 2 * OPB + so0, Bhb + (size_t)lr  * ldb + kb8);
    cp16(s + 2 * OPB + so1, Bhb + (size_t)lr1 * ldb + kb8);
    cp16(s + 3 * OPB + so0, Blb + (size_t)lr  * ldb + kb8);
    cp16(s + 3 * OPB + so1, Blb + (size_t)lr1 * ldb + kb8);
    asm volatile("cp.async.commit_group;" ::: "memory");
}

// OM=0: fp32 C out.  OM=1: bf16 hi/lo out (Ch, Cl), with scale applied after bias.
template<int OM>
__global__ __launch_bounds__(256, 1)
void gemm_mma(const __nv_bfloat16* __restrict__ Ah, const __nv_bfloat16* __restrict__ Al, int lda,
              const __nv_bfloat16* __restrict__ Bh, const __nv_bfloat16* __restrict__ Bl, int ldb,
              const float* __restrict__ bias, float* __restrict__ C,
              __nv_bfloat16* __restrict__ Ch, __nv_bfloat16* __restrict__ Cl,
              float scale, int ldc, int K)
{
    extern __shared__ char smraw[];
    const uint32_t sb = smem_u32(smraw);
    const int tid = threadIdx.x;
    const int l = tid & 31, w = tid >> 5;
    const int wm = (w >> 2) * 64, wn = (w & 3) * 32;
    const int mb = blockIdx.y * 128, nb = blockIdx.x * 128;

    const __nv_bfloat16* Ahb = Ah + (size_t)mb * lda;
    const __nv_bfloat16* Alb = Al + (size_t)mb * lda;
    const __nv_bfloat16* Bhb = Bh + (size_t)nb * ldb;
    const __nv_bfloat16* Blb = Bl + (size_t)nb * ldb;

    const int lr  = tid >> 2;
    const int lr1 = lr + 64;
    const int lkc = tid & 3;
    const uint32_t so0 = (uint32_t)(lr  * 64 + ((lkc ^ ((lr  >> 1) & 3)) << 4));
    const uint32_t so1 = (uint32_t)(lr1 * 64 + ((lkc ^ ((lr1 >> 1) & 3)) << 4));

    const int rA = l & 15, kselA = l >> 4, swA = (rA >> 1) & 3;
    const uint32_t aRow = (uint32_t)((wm + rA) * 64);
    const uint32_t aK0 = (uint32_t)(((0 + kselA) ^ swA) << 4);
    const uint32_t aK1 = (uint32_t)(((2 + kselA) ^ swA) << 4);
    const int rB = (l & 7) + ((l >> 4) << 3), kselB = (l >> 3) & 1, swB = (rB >> 1) & 3;
    const uint32_t bRow = (uint32_t)((wn + rB) * 64);
    const uint32_t bK0 = (uint32_t)(((0 + kselB) ^ swB) << 4);
    const uint32_t bK1 = (uint32_t)(((2 + kselB) ^ swB) << 4);

    float acc[4][4][4];
#pragma unroll
    for (int mi = 0; mi < 4; mi++)
#pragma unroll
        for (int ni = 0; ni < 4; ni++)
#pragma unroll
            for (int i = 0; i < 4; i++) acc[mi][ni][i] = 0.0f;

    const int NKB = K >> 5;
    issue_stage(sb, 0, 0,  Ahb, Alb, Bhb, Blb, lda, ldb, lr, lr1, lkc, so0, so1);
    issue_stage(sb, 1, 32, Ahb, Alb, Bhb, Blb, lda, ldb, lr, lr1, lkc, so0, so1);

    for (int kb = 0; kb < NKB; kb++) {
        if (kb < NKB - 2) asm volatile("cp.async.wait_group 1;" ::: "memory");
        else              asm volatile("cp.async.wait_group 0;" ::: "memory");
        __syncthreads();
        if (kb + 2 < NKB)
            issue_stage(sb, (kb + 2) % 3, (kb + 2) * 32,
                        Ahb, Alb, Bhb, Blb, lda, ldb, lr, lr1, lkc, so0, so1);

        const uint32_t s = sb + (uint32_t)(kb % 3) * STGB;
#pragma unroll
        for (int kk = 0; kk < 2; kk++) {
            const uint32_t aK = kk ? aK1 : aK0;
            const uint32_t bK = kk ? bK1 : bK0;
            uint32_t ah[4][4], al4[4][4], bh[2][4], bl4[2][4];
#pragma unroll
            for (int mi = 0; mi < 4; mi++) {
                ldsm4(ah[mi],  s +           aRow + mi * 1024 + aK);
                ldsm4(al4[mi], s + OPB +     aRow + mi * 1024 + aK);
            }
#pragma unroll
            for (int g = 0; g < 2; g++) {
                ldsm4(bh[g],  s + 2 * OPB + bRow + g * 1024 + bK);
                ldsm4(bl4[g], s + 3 * OPB + bRow + g * 1024 + bK);
            }
#pragma unroll
            for (int mi = 0; mi < 4; mi++)
#pragma unroll
                for (int ni = 0; ni < 4; ni++) {
                    uint32_t* bhp = &bh[ni >> 1][(ni & 1) * 2];
                    uint32_t* blp = &bl4[ni >> 1][(ni & 1) * 2];
                    mma_bf16(acc[mi][ni], ah[mi],  bhp);
                    mma_bf16(acc[mi][ni], ah[mi],  blp);
                    mma_bf16(acc[mi][ni], al4[mi], bhp);
                }
        }
    }

    const int cr = l >> 2, cc2 = (l & 3) * 2;
#pragma unroll
    for (int ni = 0; ni < 4; ni++) {
        const int col = nb + wn + ni * 8 + cc2;
        const float b0 = bias[col], b1 = bias[col + 1];
#pragma unroll
        for (int mi = 0; mi < 4; mi++) {
            const int row = mb + wm + mi * 16 + cr;
            float v0 = acc[mi][ni][0] + b0, v1 = acc[mi][ni][1] + b1;
            float v2 = acc[mi][ni][2] + b0, v3 = acc[mi][ni][3] + b1;
            if (OM == 0) {
                *(float2*)(C + (size_t)row * ldc + col) = make_float2(v0, v1);
                *(float2*)(C + (size_t)(row + 8) * ldc + col) = make_float2(v2, v3);
            } else {
                v0 *= scale; v1 *= scale; v2 *= scale; v3 *= scale;
                uint32_t h0, l0, h1, l1;
                split2(v0, v1, h0, l0);
                split2(v2, v3, h1, l1);
                *(uint32_t*)(Ch + (size_t)row * ldc + col) = h0;
                *(uint32_t*)(Cl + (size_t)row * ldc + col) = l0;
                *(uint32_t*)(Ch + (size_t)(row + 8) * ldc + col) = h1;
                *(uint32_t*)(Cl + (size_t)(row + 8) * ldc + col) = l1;
            }
        }
    }
}

// ---------------- RoPE on q,k segments of qkv (in place) ----------------
__global__ void rope_kernel(float* __restrict__ qkv)
{
    int idx = blockIdx.x * 256 + threadIdx.x;
    int i = idx & 31;
    int h = (idx >> 5) & 15;
    int m = idx >> 9;
    int s = m & (S_LEN - 1);
    float inv = (float)exp2(-(double)i * 0.41524101186091903);
    float ang = (float)s * inv;
    float c, sn;
    sincosf(ang, &sn, &c);
    size_t bse = (size_t)m * 3072 + (h << 6) + i;
    float q0 = qkv[bse], q1 = qkv[bse + 32];
    qkv[bse]        = q0 * c - q1 * sn;
    qkv[bse + 32]   = q1 * c + q0 * sn;
    float k0 = qkv[bse + 1024], k1 = qkv[bse + 1056];
    qkv[bse + 1024] = k0 * c - k1 * sn;
    qkv[bse + 1056] = k1 * c + k0 * sn;
}

// ---------------- Flash attention on mma.sync bf16x2 ----------------
// CTA: 128 q-rows (8 warps x 16), 64 k-cols per iter, D=64, 32 iters.
// smem: Qh[16K] Ql[16K] | mask[2K] | 3 stages x {Kh,Kl,Vh,Vl}[8K each]
#define ATT_MASK 32768
#define ATT_KV   34816
#define ATT_STG  32768
#define ATT_SMEM (ATT_KV + 3 * ATT_STG)   // 133120
#define NITER    32

__global__ __launch_bounds__(256, 1)
void attn_mma(const __nv_bfloat16* __restrict__ qh, const __nv_bfloat16* __restrict__ ql,
              const __nv_bfloat16* __restrict__ kh, const __nv_bfloat16* __restrict__ kl,
              const __nv_bfloat16* __restrict__ vh, const __nv_bfloat16* __restrict__ vl,
              const unsigned char* __restrict__ maskg,
              __nv_bfloat16* __restrict__ Oh, __nv_bfloat16* __restrict__ Ol)
{
    extern __shared__ char sm[];
    const uint32_t sb = smem_u32(sm);
    const int tid = threadIdx.x, l = tid & 31, w = tid >> 5;
    const int b = blockIdx.z, h = blockIdx.y, q0 = blockIdx.x << 7;
    const size_t rowbase = (size_t)b * S_LEN;
    const int h64 = h << 6;

    // ---- prologue loads: G0 = Q + mask + KV tile0 ; G1 = KV tile1 ----
    {   // Q hi/lo: 2 tiles x 128 rows x 8 chunks
        int tile = tid >> 7;
        const __nv_bfloat16* src = tile ? ql : qh;
        uint32_t dstb = sb + tile * 16384;
        int base = tid & 127;
#pragma unroll
        for (int i = 0; i < 8; i++) {
            int idx = base + i * 128; int r = idx >> 3, c = idx & 7;
            cp16(dstb + r * 128 + ((c ^ (r & 7)) << 4),
                 src + (rowbase + q0 + r) * 1024 + h64 + c * 8);
        }
        if (tid < 128) cp16(sb + ATT_MASK + tid * 16, maskg + (size_t)b * S_LEN + tid * 16);
    }
    const int kvtile = tid >> 6;
    const __nv_bfloat16* kvsrc = (kvtile == 0) ? kh : (kvtile == 1) ? kl : (kvtile == 2) ? vh : vl;
    const int kvbase = tid & 63;
#define LOAD_KV(stg, kb) do {                                                     \
        uint32_t dstb = sb + ATT_KV + (stg) * ATT_STG + kvtile * 8192;            \
        _Pragma("unroll")                                                         \
        for (int i = 0; i < 8; i++) {                                             \
            int idx = kvbase + i * 64; int r = idx >> 3, c = idx & 7;             \
            cp16(dstb + r * 128 + ((c ^ (r & 7)) << 4),                           \
                 kvsrc + (rowbase + (kb) + r) * 1024 + h64 + c * 8);              \
        }                                                                         \
        asm volatile("cp.async.commit_group;" ::: "memory");                      \
    } while (0)

    LOAD_KV(0, 0);
    LOAD_KV(1, 64);

    asm volatile("cp.async.wait_group 1;" ::: "memory");
    __syncthreads();

    // ---- Q fragments (persistent) ----
    uint32_t qfh[4][4], qfl[4][4];
    {
        int row = (w << 4) + (l & 15);
#pragma unroll
        for (int j = 0; j < 4; j++) {
            uint32_t ch = (uint32_t)(((2 * j + (l >> 4)) ^ (row & 7)) << 4);
            ldsm4(qfh[j], sb +         row * 128 + ch);
            ldsm4(qfl[j], sb + 16384 + row * 128 + ch);
        }
    }

    float o[8][4];
#pragma unroll
    for (int di = 0; di < 8; di++)
#pragma unroll
        for (int i = 0; i < 4; i++) o[di][i] = 0.0f;
    float m0 = -1e30f, m1 = -1e30f, l0 = 0.0f, l1 = 0.0f;

    const unsigned char* Ms = (const unsigned char*)sm + ATT_MASK;

    for (int kt = 0; kt < NITER; kt++) {
        if (kt < NITER - 2) asm volatile("cp.async.wait_group 1;" ::: "memory");
        else                asm volatile("cp.async.wait_group 0;" ::: "memory");
        __syncthreads();
        if (kt + 2 < NITER) LOAD_KV((kt + 2) % 3, (kt + 2) * 64);

        const uint32_t stg = sb + ATT_KV + (uint32_t)(kt % 3) * ATT_STG;
        const int kb = kt << 6;

        // ---- S = Q K^T (3-pass split), fp32 accum ----
        float S[8][4];
#pragma unroll
        for (int ni = 0; ni < 8; ni++)
#pragma unroll
            for (int i = 0; i < 4; i++) S[ni][i] = 0.0f;

#pragma unroll
        for (int j = 0; j < 4; j++) {
            uint32_t bh4[4][4], bl4[4][4];
#pragma unroll
            for (int ng = 0; ng < 4; ng++) {
                int row = (ng << 4) + (l & 7) + ((l >> 4) << 3);
                uint32_t ch = (uint32_t)(((2 * j + ((l >> 3) & 1)) ^ (row & 7)) << 4);
                ldsm4(bh4[ng], stg +        row * 128 + ch);
                ldsm4(bl4[ng], stg + 8192 + row * 128 + ch);
            }
#pragma unroll
            for (int ni = 0; ni < 8; ni++) {
                uint32_t* bp = &bh4[ni >> 1][(ni & 1) * 2];
                uint32_t* lp = &bl4[ni >> 1][(ni & 1) * 2];
                mma_bf16(S[ni], qfh[j], bp);
                mma_bf16(S[ni], qfh[j], lp);
                mma_bf16(S[ni], qfl[j], bp);
            }
        }

        // ---- mask + online softmax (rows r0 = regs 0,1 ; r1 = regs 2,3) ----
        float tm0 = -1e30f, tm1 = -1e30f;
#pragma unroll
        for (int ni = 0; ni < 8; ni++) {
            uchar2 mm = *(const uchar2*)(Ms + kb + (ni << 3) + ((l & 3) << 1));
            if (mm.x) { S[ni][0] = -1e30f; S[ni][2] = -1e30f; }
            if (mm.y) { S[ni][1] = -1e30f; S[ni][3] = -1e30f; }
            tm0 = fmaxf(tm0, fmaxf(S[ni][0], S[ni][1]));
            tm1 = fmaxf(tm1, fmaxf(S[ni][2], S[ni][3]));
        }
        tm0 = fmaxf(tm0, __shfl_xor_sync(0xffffffffu, tm0, 1));
        tm0 = fmaxf(tm0, __shfl_xor_sync(0xffffffffu, tm0, 2));
        tm1 = fmaxf(tm1, __shfl_xor_sync(0xffffffffu, tm1, 1));
        tm1 = fmaxf(tm1, __shfl_xor_sync(0xffffffffu, tm1, 2));
        float mn0 = fmaxf(m0, tm0), mn1 = fmaxf(m1, tm1);
        float c0 = __expf(m0 - mn0), c1 = __expf(m1 - mn1);
        m0 = mn0; m1 = mn1;
        float rs0 = 0.0f, rs1 = 0.0f;
#pragma unroll
        for (int ni = 0; ni < 8; ni++) {
            S[ni][0] = __expf(S[ni][0] - mn0); rs0 += S[ni][0];
            S[ni][1] = __expf(S[ni][1] - mn0); rs0 += S[ni][1];
            S[ni][2] = __expf(S[ni][2] - mn1); rs1 += S[ni][2];
            S[ni][3] = __expf(S[ni][3] - mn1); rs1 += S[ni][3];
        }
        rs0 += __shfl_xor_sync(0xffffffffu, rs0, 1);
        rs0 += __shfl_xor_sync(0xffffffffu, rs0, 2);
        rs1 += __shfl_xor_sync(0xffffffffu, rs1, 1);
        rs1 += __shfl_xor_sync(0xffffffffu, rs1, 2);
        l0 = l0 * c0 + rs0; l1 = l1 * c1 + rs1;
#pragma unroll
        for (int di = 0; di < 8; di++) {
            o[di][0] *= c0; o[di][1] *= c0; o[di][2] *= c1; o[di][3] *= c1;
        }

        // ---- O += P V (3-pass split; P from S fragments, in registers) ----
#pragma unroll
        for (int js = 0; js < 4; js++) {
            uint32_t pha[4], pla[4];
            {
                const int t0 = 2 * js, t1 = t0 + 1;
                split2(S[t0][0], S[t0][1], pha[0], pla[0]);
                split2(S[t0][2], S[t0][3], pha[1], pla[1]);
                split2(S[t1][0], S[t1][1], pha[2], pla[2]);
                split2(S[t1][2], S[t1][3], pha[3], pla[3]);
            }
            uint32_t vh4[4][4], vl4[4][4];
#pragma unroll
            for (int dg = 0; dg < 4; dg++) {
                int row = (js << 4) + (l & 7) + (((l >> 3) & 1) << 3);
                uint32_t ch = (uint32_t)(((2 * dg + (l >> 4)) ^ (row & 7)) << 4);
                ldsm4t(vh4[dg], stg + 16384 + row * 128 + ch);
                ldsm4t(vl4[dg], stg + 24576 + row * 128 + ch);
            }
#pragma unroll
            for (int di = 0; di < 8; di++) {
                uint32_t* vp = &vh4[di >> 1][(di & 1) * 2];
                uint32_t* lp = &vl4[di >> 1][(di & 1) * 2];
                mma_bf16(o[di], pha, vp);
                mma_bf16(o[di], pha, lp);
                mma_bf16(o[di], pla, vp);
            }
        }
    }

    // ---- epilogue: normalize, split to bf16 hi/lo, store ----
    const float inv0 = 1.0f / l0, inv1 = 1.0f / l1;
    const int r0 = q0 + (w << 4) + (l >> 2);
#pragma unroll
    for (int di = 0; di < 8; di++) {
        const int col = h64 + (di << 3) + ((l & 3) << 1);
        uint32_t h0, lo0, h1, lo1;
        split2(o[di][0] * inv0, o[di][1] * inv0, h0, lo0);
        split2(o[di][2] * inv1, o[di][3] * inv1, h1, lo1);
        *(uint32_t*)(Oh + (rowbase + r0) * 1024 + col) = h0;
        *(uint32_t*)(Ol + (rowbase + r0) * 1024 + col) = lo0;
        *(uint32_t*)(Oh + (rowbase + r0 + 8) * 1024 + col) = h1;
        *(uint32_t*)(Ol + (rowbase + r0 + 8) * 1024 + col) = lo1;
    }
}

// ---------------- launch ----------------
extern "C" void kernel_launch(void* const* d_in, const int* in_sizes, int n_in,
                              void* d_out, int out_size)
{
    const float* x     = (const float*)d_in[0];
    const float* w_in  = (const float*)d_in[1];
    const float* b_in  = (const float*)d_in[2];
    const float* w_out = (const float*)d_in[3];
    const float* b_out = (const float*)d_in[4];
    const unsigned char* mask = (const unsigned char*)d_in[5];
    float* out = (float*)d_out;

    float* qkv;
    cudaGetSymbolAddress((void**)&qkv, g_qkv);
    __nv_bfloat16 *xh, *xl, *wih, *wil, *woh, *wol, *qkh, *qkl;
    __nv_bfloat16 *qh, *ql, *kh, *kl, *vh, *vl, *cth, *ctl;
    cudaGetSymbolAddress((void**)&xh,  g_xh);  cudaGetSymbolAddress((void**)&xl,  g_xl);
    cudaGetSymbolAddress((void**)&wih, g_wih); cudaGetSymbolAddress((void**)&wil, g_wil);
    cudaGetSymbolAddress((void**)&woh, g_woh); cudaGetSymbolAddress((void**)&wol, g_wol);
    cudaGetSymbolAddress((void**)&qkh, g_qkh); cudaGetSymbolAddress((void**)&qkl, g_qkl);
    cudaGetSymbolAddress((void**)&qh,  g_qh);  cudaGetSymbolAddress((void**)&ql,  g_ql);
    cudaGetSymbolAddress((void**)&kh,  g_kh);  cudaGetSymbolAddress((void**)&kl,  g_kl);
    cudaGetSymbolAddress((void**)&vh,  g_vh);  cudaGetSymbolAddress((void**)&vl,  g_vl);
    cudaGetSymbolAddress((void**)&cth, g_cth); cudaGetSymbolAddress((void**)&ctl, g_ctl);

    cudaFuncSetAttribute(gemm_mma<0>, cudaFuncAttributeMaxDynamicSharedMemorySize, GEMM_SMEM);
    cudaFuncSetAttribute(gemm_mma<1>, cudaFuncAttributeMaxDynamicSharedMemorySize, GEMM_SMEM);
    cudaFuncSetAttribute(attn_mma,    cudaFuncAttributeMaxDynamicSharedMemorySize, ATT_SMEM);

    // split inputs
    split_kernel<<<8192, 256>>>(x,     xh,  xl,  2097152);
    split_kernel<<<3072, 256>>>(w_in,  wih, wil, 786432);
    split_kernel<<<1024, 256>>>(w_out, woh, wol, 262144);

    // 1) qkv = x @ Win^T + b (fp32 out, 8192 x 3072)
    gemm_mma<0><<<dim3(24, 64), 256, GEMM_SMEM>>>(xh, xl, 1024, wih, wil, 1024,
                                                  b_in, qkv, nullptr, nullptr, 1.0f, 3072, 1024);
    // 2) RoPE in place, then split qkv
    rope_kernel<<<16384, 256>>>(qkv);
    split_kernel<<<24576, 256>>>(qkv, qkh, qkl, 6291456);
    // 3) second projection -> bf16 hi/lo (q scaled by 1/sqrt(D))
    gemm_mma<1><<<dim3(8, 64), 256, GEMM_SMEM>>>(qkh,        qkl,        3072, wih,               wil,               1024,
                                                 b_in,        nullptr, qh, ql, 0.125f, 1024, 1024);
    gemm_mma<1><<<dim3(8, 64), 256, GEMM_SMEM>>>(qkh + 1024, qkl + 1024, 3072, wih + 1024 * 1024, wil + 1024 * 1024, 1024,
                                                 b_in + 1024, nullptr, kh, kl, 1.0f,   1024, 1024);
    gemm_mma<1><<<dim3(8, 64), 256, GEMM_SMEM>>>(qkh + 2048, qkl + 2048, 3072, wih + 2048 * 1024, wil + 2048 * 1024, 1024,
                                                 b_in + 2048, nullptr, vh, vl, 1.0f,   1024, 1024);
    // 4) attention on tensor cores -> ctx hi/lo
    attn_mma<<<dim3(16, 16, 4), 256, ATT_SMEM>>>(qh, ql, kh, kl, vh, vl, mask, cth, ctl);
    // 5) out = ctx @ Wout^T + b (fp32 out)
    gemm_mma<0><<<dim3(8, 64), 256, GEMM_SMEM>>>(cth, ctl, 1024, woh, wol, 1024,
                                                 b_out, out, nullptr, nullptr, 1.0f, 1024, 1024);
}

// round 10
// speedup vs baseline: 2.9497x; 1.7023x over previous
#include <cuda_runtime.h>
#include <cuda_bf16.h>
#include <math.h>
#include <stdint.h>

#define E_DIM 1024
#define S_LEN 2048

// ---------------- scratch (no allocation allowed) ----------------
__device__ __nv_bfloat16 g_xh [8388608],  g_xl [8388608];
__device__ __nv_bfloat16 g_wih[3145728],  g_wil[3145728];
__device__ __nv_bfloat16 g_woh[1048576],  g_wol[1048576];
__device__ __nv_bfloat16 g_qkh[25165824], g_qkl[25165824];  // rope'd qkv hi/lo
__device__ __nv_bfloat16 g_qh [8388608],  g_ql [8388608];   // q2 hi/lo (scaled 0.125)
__device__ __nv_bfloat16 g_kh [8388608],  g_kl [8388608];
__device__ __nv_bfloat16 g_vh [8388608],  g_vl [8388608];
__device__ __nv_bfloat16 g_cth[8388608],  g_ctl[8388608];   // ctx hi/lo

// ---------------- helpers ----------------
__device__ __forceinline__ uint32_t smem_u32(const void* p) {
    uint32_t a;
    asm("{ .reg .u64 t; cvta.to.shared.u64 t, %1; cvt.u32.u64 %0, t; }" : "=r"(a) : "l"(p));
    return a;
}
__device__ __forceinline__ void cp16(uint32_t s, const void* g) {
    asm volatile("cp.async.cg.shared.global [%0], [%1], 16;" :: "r"(s), "l"(g));
}
__device__ __forceinline__ void ldsm4(uint32_t* r, uint32_t a) {
    asm volatile("ldmatrix.sync.aligned.m8n8.x4.shared.b16 {%0,%1,%2,%3}, [%4];"
        : "=r"(r[0]), "=r"(r[1]), "=r"(r[2]), "=r"(r[3]) : "r"(a));
}
__device__ __forceinline__ void ldsm4t(uint32_t* r, uint32_t a) {
    asm volatile("ldmatrix.sync.aligned.m8n8.x4.trans.shared.b16 {%0,%1,%2,%3}, [%4];"
        : "=r"(r[0]), "=r"(r[1]), "=r"(r[2]), "=r"(r[3]) : "r"(a));
}
__device__ __forceinline__ void mma_bf16(float* c, const uint32_t* a, const uint32_t* b) {
    asm volatile("mma.sync.aligned.m16n8k16.row.col.f32.bf16.bf16.f32 "
        "{%0,%1,%2,%3}, {%4,%5,%6,%7}, {%8,%9}, {%0,%1,%2,%3};"
        : "+f"(c[0]), "+f"(c[1]), "+f"(c[2]), "+f"(c[3])
        : "r"(a[0]), "r"(a[1]), "r"(a[2]), "r"(a[3]), "r"(b[0]), "r"(b[1]));
}
__device__ __forceinline__ uint32_t pack2(__nv_bfloat16 a, __nv_bfloat16 b) {
    unsigned short ua = *(unsigned short*)&a, ub = *(unsigned short*)&b;
    return (uint32_t)ua | ((uint32_t)ub << 16);
}
__device__ __forceinline__ void split2(float x, float y, uint32_t& hi, uint32_t& lo) {
    __nv_bfloat16 hx = __float2bfloat16_rn(x);
    __nv_bfloat16 hy = __float2bfloat16_rn(y);
    __nv_bfloat16 lx = __float2bfloat16_rn(x - __bfloat162float(hx));
    __nv_bfloat16 ly = __float2bfloat16_rn(y - __bfloat162float(hy));
    hi = pack2(hx, hy); lo = pack2(lx, ly);
}

// ---------------- split fp32 -> bf16 hi + bf16 lo ----------------
__global__ void split_kernel(const float* __restrict__ src,
                             __nv_bfloat16* __restrict__ hi,
                             __nv_bfloat16* __restrict__ lo, int n4)
{
    int q = blockIdx.x * 256 + threadIdx.x;
    if (q >= n4) return;
    int i = q << 2;
    float4 v = *(const float4*)(src + i);
    float f[4] = {v.x, v.y, v.z, v.w};
    __nv_bfloat16 h[4], l[4];
#pragma unroll
    for (int j = 0; j < 4; j++) {
        h[j] = __float2bfloat16_rn(f[j]);
        l[j] = __float2bfloat16_rn(f[j] - __bfloat162float(h[j]));
    }
    *(__nv_bfloat162*)(hi + i)     = __nv_bfloat162(h[0], h[1]);
    *(__nv_bfloat162*)(hi + i + 2) = __nv_bfloat162(h[2], h[3]);
    *(__nv_bfloat162*)(lo + i)     = __nv_bfloat162(l[0], l[1]);
    *(__nv_bfloat162*)(lo + i + 2) = __nv_bfloat162(l[2], l[3]);
}

// ---------------- mma.sync bf16x2 GEMM: C[M,N] = A[M,K] @ B[N,K]^T + bias ----------------
// OM=0: fp32 out.  OM=1: bf16 hi/lo out, scale after bias.
// OM=2: RoPE (for N-tiles 0..15) + bf16 hi/lo out  [GEMM1 fused epilogue]
#define OPB       8192
#define STGB      (4 * OPB)
#define GEMM_SMEM (3 * STGB)

__device__ __forceinline__ void issue_stage(uint32_t sb, int stg, int k0,
    const __nv_bfloat16* Ahb, const __nv_bfloat16* Alb,
    const __nv_bfloat16* Bhb, const __nv_bfloat16* Blb,
    int lda, int ldb, int lr, int lr1, int lkc, uint32_t so0, uint32_t so1)
{
    uint32_t s = sb + (uint32_t)stg * STGB;
    const int kb8 = k0 + lkc * 8;
    cp16(s +           so0, Ahb + (size_t)lr  * lda + kb8);
    cp16(s +           so1, Ahb + (size_t)lr1 * lda + kb8);
    cp16(s + OPB +     so0, Alb + (size_t)lr  * lda + kb8);
    cp16(s + OPB +     so1, Alb + (size_t)lr1 * lda + kb8);
    cp16(s + 2 * OPB + so0, Bhb + (size_t)lr  * ldb + kb8);
    cp16(s + 2 * OPB + so1, Bhb + (size_t)lr1 * ldb + kb8);
    cp16(s + 3 * OPB + so0, Blb + (size_t)lr  * ldb + kb8);
    cp16(s + 3 * OPB + so1, Blb + (size_t)lr1 * ldb + kb8);
    asm volatile("cp.async.commit_group;" ::: "memory");
}

template<int OM>
__global__ __launch_bounds__(256, 1)
void gemm_mma(const __nv_bfloat16* __restrict__ Ah, const __nv_bfloat16* __restrict__ Al, int lda,
              const __nv_bfloat16* __restrict__ Bh, const __nv_bfloat16* __restrict__ Bl, int ldb,
              const float* __restrict__ bias, float* __restrict__ C,
              __nv_bfloat16* __restrict__ Ch, __nv_bfloat16* __restrict__ Cl,
              float scale, int ldc, int K)
{
    extern __shared__ char smraw[];
    const uint32_t sb = smem_u32(smraw);
    const int tid = threadIdx.x;
    const int l = tid & 31, w = tid >> 5;
    const int wm = (w >> 2) * 64, wn = (w & 3) * 32;
    const int mb = blockIdx.y * 128, nb = blockIdx.x * 128;

    const __nv_bfloat16* Ahb = Ah + (size_t)mb * lda;
    const __nv_bfloat16* Alb = Al + (size_t)mb * lda;
    const __nv_bfloat16* Bhb = Bh + (size_t)nb * ldb;
    const __nv_bfloat16* Blb = Bl + (size_t)nb * ldb;

    const int lr  = tid >> 2;
    const int lr1 = lr + 64;
    const int lkc = tid & 3;
    const uint32_t so0 = (uint32_t)(lr  * 64 + ((lkc ^ ((lr  >> 1) & 3)) << 4));
    const uint32_t so1 = (uint32_t)(lr1 * 64 + ((lkc ^ ((lr1 >> 1) & 3)) << 4));

    const int rA = l & 15, kselA = l >> 4, swA = (rA >> 1) & 3;
    const uint32_t aRow = (uint32_t)((wm + rA) * 64);
    const uint32_t aK0 = (uint32_t)(((0 + kselA) ^ swA) << 4);
    const uint32_t aK1 = (uint32_t)(((2 + kselA) ^ swA) << 4);
    const int rB = (l & 7) + ((l >> 4) << 3), kselB = (l >> 3) & 1, swB = (rB >> 1) & 3;
    const uint32_t bRow = (uint32_t)((wn + rB) * 64);
    const uint32_t bK0 = (uint32_t)(((0 + kselB) ^ swB) << 4);
    const uint32_t bK1 = (uint32_t)(((2 + kselB) ^ swB) << 4);

    float acc[4][4][4];
#pragma unroll
    for (int mi = 0; mi < 4; mi++)
#pragma unroll
        for (int ni = 0; ni < 4; ni++)
#pragma unroll
            for (int i = 0; i < 4; i++) acc[mi][ni][i] = 0.0f;

    const int NKB = K >> 5;
    issue_stage(sb, 0, 0,  Ahb, Alb, Bhb, Blb, lda, ldb, lr, lr1, lkc, so0, so1);
    issue_stage(sb, 1, 32, Ahb, Alb, Bhb, Blb, lda, ldb, lr, lr1, lkc, so0, so1);

    for (int kb = 0; kb < NKB; kb++) {
        if (kb < NKB - 2) asm volatile("cp.async.wait_group 1;" ::: "memory");
        else              asm volatile("cp.async.wait_group 0;" ::: "memory");
        __syncthreads();
        if (kb + 2 < NKB)
            issue_stage(sb, (kb + 2) % 3, (kb + 2) * 32,
                        Ahb, Alb, Bhb, Blb, lda, ldb, lr, lr1, lkc, so0, so1);

        const uint32_t s = sb + (uint32_t)(kb % 3) * STGB;
#pragma unroll
        for (int kk = 0; kk < 2; kk++) {
            const uint32_t aK = kk ? aK1 : aK0;
            const uint32_t bK = kk ? bK1 : bK0;
            uint32_t ah[4][4], al4[4][4], bh[2][4], bl4[2][4];
#pragma unroll
            for (int mi = 0; mi < 4; mi++) {
                ldsm4(ah[mi],  s +           aRow + mi * 1024 + aK);
                ldsm4(al4[mi], s + OPB +     aRow + mi * 1024 + aK);
            }
#pragma unroll
            for (int g = 0; g < 2; g++) {
                ldsm4(bh[g],  s + 2 * OPB + bRow + g * 1024 + bK);
                ldsm4(bl4[g], s + 3 * OPB + bRow + g * 1024 + bK);
            }
#pragma unroll
            for (int mi = 0; mi < 4; mi++)
#pragma unroll
                for (int ni = 0; ni < 4; ni++) {
                    uint32_t* bhp = &bh[ni >> 1][(ni & 1) * 2];
                    uint32_t* blp = &bl4[ni >> 1][(ni & 1) * 2];
                    mma_bf16(acc[mi][ni], ah[mi],  bhp);
                    mma_bf16(acc[mi][ni], ah[mi],  blp);
                    mma_bf16(acc[mi][ni], al4[mi], bhp);
                }
        }
    }

    const int cr = l >> 2, cc2 = (l & 3) * 2;

    if (OM == 2) {
        // ---- fused RoPE + split epilogue (GEMM1) ----
        __syncthreads();                       // mainloop smem reads done
        float* sE = (float*)smraw;             // 128 x 132 fp32 staging
#pragma unroll
        for (int ni = 0; ni < 4; ni++) {
            const int colg = nb + wn + ni * 8 + cc2;
            const float b0 = bias[colg], b1 = bias[colg + 1];
            const int colL = wn + ni * 8 + cc2;
#pragma unroll
            for (int mi = 0; mi < 4; mi++) {
                const int rowL = wm + mi * 16 + cr;
                sE[rowL * 132 + colL]           = acc[mi][ni][0] + b0;
                sE[rowL * 132 + colL + 1]       = acc[mi][ni][1] + b1;
                sE[(rowL + 8) * 132 + colL]     = acc[mi][ni][2] + b0;
                sE[(rowL + 8) * 132 + colL + 1] = acc[mi][ni][3] + b1;
            }
        }
        __syncthreads();
        const bool doRope = (blockIdx.x < 16);      // q,k tiles; v tiles pass through
        const int i0 = (tid & 15) << 1;
        const int hh = (tid >> 4) & 1;
        const int rb0 = tid >> 5;
        const float invA = (float)exp2(-(double)i0 * 0.41524101186091903);
        const float invB = (float)exp2(-(double)(i0 + 1) * 0.41524101186091903);
        const int colL = hh * 64 + i0;
#pragma unroll 4
        for (int rr = 0; rr < 16; rr++) {
            const int row = rb0 + (rr << 3);
            float cA = 1.0f, sA = 0.0f, cB = 1.0f, sB = 0.0f;
            if (doRope) {
                const float sPos = (float)((mb + row) & (S_LEN - 1));
                sincosf(sPos * invA, &sA, &cA);
                sincosf(sPos * invB, &sB, &cB);
            }
            float2 x0 = *(float2*)&sE[row * 132 + colL];
            float2 x1 = *(float2*)&sE[row * 132 + colL + 32];
            float r00 = x0.x * cA - x1.x * sA, r01 = x0.y * cB - x1.y * sB;
            float r10 = x1.x * cA + x0.x * sA, r11 = x1.y * cB + x0.y * sB;
            uint32_t h0, l0, h1, l1;
            split2(r00, r01, h0, l0);
            split2(r10, r11, h1, l1);
            const size_t base = (size_t)(mb + row) * ldc + nb + colL;
            *(uint32_t*)(Ch + base)      = h0;
            *(uint32_t*)(Cl + base)      = l0;
            *(uint32_t*)(Ch + base + 32) = h1;
            *(uint32_t*)(Cl + base + 32) = l1;
        }
        return;
    }

#pragma unroll
    for (int ni = 0; ni < 4; ni++) {
        const int col = nb + wn + ni * 8 + cc2;
        const float b0 = bias[col], b1 = bias[col + 1];
#pragma unroll
        for (int mi = 0; mi < 4; mi++) {
            const int row = mb + wm + mi * 16 + cr;
            float v0 = acc[mi][ni][0] + b0, v1 = acc[mi][ni][1] + b1;
            float v2 = acc[mi][ni][2] + b0, v3 = acc[mi][ni][3] + b1;
            if (OM == 0) {
                *(float2*)(C + (size_t)row * ldc + col) = make_float2(v0, v1);
                *(float2*)(C + (size_t)(row + 8) * ldc + col) = make_float2(v2, v3);
            } else {
                v0 *= scale; v1 *= scale; v2 *= scale; v3 *= scale;
                uint32_t h0, l0, h1, l1;
                split2(v0, v1, h0, l0);
                split2(v2, v3, h1, l1);
                *(uint32_t*)(Ch + (size_t)row * ldc + col) = h0;
                *(uint32_t*)(Cl + (size_t)row * ldc + col) = l0;
                *(uint32_t*)(Ch + (size_t)(row + 8) * ldc + col) = h1;
                *(uint32_t*)(Cl + (size_t)(row + 8) * ldc + col) = l1;
            }
        }
    }
}

// ---------------- Flash attention on mma.sync bf16x2 ----------------
// 128 threads (4 warps x 16 q-rows = 64 rows/CTA), 64 k-cols/iter, 2-stage KV,
// 2 CTAs/SM.  smem: Qh[8K] Ql[8K] mask[2K] | 2 stages x {Kh,Kl,Vh,Vl}[8K each]
#define ATT_QL   8192
#define ATT_MASK 16384
#define ATT_KV   18432
#define ATT_STG  32768
#define ATT_SMEM (ATT_KV + 2 * ATT_STG)   // 83968
#define NITER    32

__global__ __launch_bounds__(128, 2)
void attn_mma(const __nv_bfloat16* __restrict__ qh, const __nv_bfloat16* __restrict__ ql,
              const __nv_bfloat16* __restrict__ kh, const __nv_bfloat16* __restrict__ kl,
              const __nv_bfloat16* __restrict__ vh, const __nv_bfloat16* __restrict__ vl,
              const unsigned char* __restrict__ maskg,
              __nv_bfloat16* __restrict__ Oh, __nv_bfloat16* __restrict__ Ol)
{
    extern __shared__ char sm[];
    const uint32_t sb = smem_u32(sm);
    const int tid = threadIdx.x, l = tid & 31, w = tid >> 5;
    const int b = blockIdx.z, h = blockIdx.y, q0 = blockIdx.x << 6;
    const size_t rowbase = (size_t)b * S_LEN;
    const int h64 = h << 6;

    // ---- prologue: Q (hi/lo) + mask + KV stage0 in group A; KV stage1 group B ----
    {
        const int tile = tid >> 6;                        // 0: hi, 1: lo
        const __nv_bfloat16* src = tile ? ql : qh;
        const uint32_t dstb = sb + tile * ATT_QL;
        const int base = tid & 63;
#pragma unroll
        for (int i = 0; i < 8; i++) {
            int idx = base + i * 64; int r = idx >> 3, c = idx & 7;
            cp16(dstb + r * 128 + ((c ^ (r & 7)) << 4),
                 src + (rowbase + q0 + r) * 1024 + h64 + c * 8);
        }
        cp16(sb + ATT_MASK + tid * 16, maskg + (size_t)b * S_LEN + tid * 16);
    }
    const int kvtile = tid >> 5;
    const __nv_bfloat16* kvsrc = (kvtile == 0) ? kh : (kvtile == 1) ? kl : (kvtile == 2) ? vh : vl;
    const int kvbase = tid & 31;
#define LOAD_KV(stg, kb) do {                                                     \
        uint32_t dstb = sb + ATT_KV + (stg) * ATT_STG + kvtile * 8192;            \
        _Pragma("unroll")                                                         \
        for (int i = 0; i < 16; i++) {                                            \
            int idx = kvbase + i * 32; int r = idx >> 3, c = idx & 7;             \
            cp16(dstb + r * 128 + ((c ^ (r & 7)) << 4),                           \
                 kvsrc + (rowbase + (kb) + r) * 1024 + h64 + c * 8);              \
        }                                                                         \
        asm volatile("cp.async.commit_group;" ::: "memory");                      \
    } while (0)

    LOAD_KV(0, 0);      // group A (Q + mask + KV0)
    LOAD_KV(1, 64);     // group B (KV1)

    asm volatile("cp.async.wait_group 1;" ::: "memory");
    __syncthreads();

    // ---- Q fragments (persistent) ----
    uint32_t qfh[4][4], qfl[4][4];
    {
        int row = (w << 4) + (l & 15);
#pragma unroll
        for (int j = 0; j < 4; j++) {
            uint32_t ch = (uint32_t)(((2 * j + (l >> 4)) ^ (row & 7)) << 4);
            ldsm4(qfh[j], sb +          row * 128 + ch);
            ldsm4(qfl[j], sb + ATT_QL + row * 128 + ch);
        }
    }

    float o[8][4];
#pragma unroll
    for (int di = 0; di < 8; di++)
#pragma unroll
        for (int i = 0; i < 4; i++) o[di][i] = 0.0f;
    float m0 = -1e30f, m1 = -1e30f, l0 = 0.0f, l1 = 0.0f;

    const unsigned char* Ms = (const unsigned char*)sm + ATT_MASK;

    for (int kt = 0; kt < NITER; kt++) {
        if (kt > 0) {
            if (kt < 30) asm volatile("cp.async.wait_group 1;" ::: "memory");
            else         asm volatile("cp.async.wait_group 0;" ::: "memory");
            __syncthreads();
        }
        const uint32_t stg = sb + ATT_KV + (uint32_t)(kt & 1) * ATT_STG;
        const int kb = kt << 6;

        // ---- S = Q K^T (3-pass split) ----
        float S[8][4];
#pragma unroll
        for (int ni = 0; ni < 8; ni++)
#pragma unroll
            for (int i = 0; i < 4; i++) S[ni][i] = 0.0f;

#pragma unroll
        for (int j = 0; j < 4; j++) {
            uint32_t bh4[4][4], bl4[4][4];
#pragma unroll
            for (int ng = 0; ng < 4; ng++) {
                int row = (ng << 4) + (l & 7) + ((l >> 4) << 3);
                uint32_t ch = (uint32_t)(((2 * j + ((l >> 3) & 1)) ^ (row & 7)) << 4);
                ldsm4(bh4[ng], stg +        row * 128 + ch);
                ldsm4(bl4[ng], stg + 8192 + row * 128 + ch);
            }
#pragma unroll
            for (int ni = 0; ni < 8; ni++) {
                uint32_t* bp = &bh4[ni >> 1][(ni & 1) * 2];
                uint32_t* lp = &bl4[ni >> 1][(ni & 1) * 2];
                mma_bf16(S[ni], qfh[j], bp);
                mma_bf16(S[ni], qfh[j], lp);
                mma_bf16(S[ni], qfl[j], bp);
            }
        }

        // ---- mask + online softmax ----
        float tm0 = -1e30f, tm1 = -1e30f;
#pragma unroll
        for (int ni = 0; ni < 8; ni++) {
            uchar2 mm = *(const uchar2*)(Ms + kb + (ni << 3) + ((l & 3) << 1));
            if (mm.x) { S[ni][0] = -1e30f; S[ni][2] = -1e30f; }
            if (mm.y) { S[ni][1] = -1e30f; S[ni][3] = -1e30f; }
            tm0 = fmaxf(tm0, fmaxf(S[ni][0], S[ni][1]));
            tm1 = fmaxf(tm1, fmaxf(S[ni][2], S[ni][3]));
        }
        tm0 = fmaxf(tm0, __shfl_xor_sync(0xffffffffu, tm0, 1));
        tm0 = fmaxf(tm0, __shfl_xor_sync(0xffffffffu, tm0, 2));
        tm1 = fmaxf(tm1, __shfl_xor_sync(0xffffffffu, tm1, 1));
        tm1 = fmaxf(tm1, __shfl_xor_sync(0xffffffffu, tm1, 2));
        float mn0 = fmaxf(m0, tm0), mn1 = fmaxf(m1, tm1);
        float c0 = __expf(m0 - mn0), c1 = __expf(m1 - mn1);
        m0 = mn0; m1 = mn1;
        float rs0 = 0.0f, rs1 = 0.0f;
#pragma unroll
        for (int ni = 0; ni < 8; ni++) {
            S[ni][0] = __expf(S[ni][0] - mn0); rs0 += S[ni][0];
            S[ni][1] = __expf(S[ni][1] - mn0); rs0 += S[ni][1];
            S[ni][2] = __expf(S[ni][2] - mn1); rs1 += S[ni][2];
            S[ni][3] = __expf(S[ni][3] - mn1); rs1 += S[ni][3];
        }
        rs0 += __shfl_xor_sync(0xffffffffu, rs0, 1);
        rs0 += __shfl_xor_sync(0xffffffffu, rs0, 2);
        rs1 += __shfl_xor_sync(0xffffffffu, rs1, 1);
        rs1 += __shfl_xor_sync(0xffffffffu, rs1, 2);
        l0 = l0 * c0 + rs0; l1 = l1 * c1 + rs1;
#pragma unroll
        for (int di = 0; di < 8; di++) {
            o[di][0] *= c0; o[di][1] *= c0; o[di][2] *= c1; o[di][3] *= c1;
        }

        // ---- O += P V (3-pass split; P in registers) ----
#pragma unroll
        for (int js = 0; js < 4; js++) {
            uint32_t pha[4], pla[4];
            {
                const int t0 = 2 * js, t1 = t0 + 1;
                split2(S[t0][0], S[t0][1], pha[0], pla[0]);
                split2(S[t0][2], S[t0][3], pha[1], pla[1]);
                split2(S[t1][0], S[t1][1], pha[2], pla[2]);
                split2(S[t1][2], S[t1][3], pha[3], pla[3]);
            }
            uint32_t vh4[4][4], vl4[4][4];
#pragma unroll
            for (int dg = 0; dg < 4; dg++) {
                int row = (js << 4) + (l & 7) + (((l >> 3) & 1) << 3);
                uint32_t ch = (uint32_t)(((2 * dg + (l >> 4)) ^ (row & 7)) << 4);
                ldsm4t(vh4[dg], stg + 16384 + row * 128 + ch);
                ldsm4t(vl4[dg], stg + 24576 + row * 128 + ch);
            }
#pragma unroll
            for (int di = 0; di < 8; di++) {
                uint32_t* vp = &vh4[di >> 1][(di & 1) * 2];
                uint32_t* lp = &vl4[di >> 1][(di & 1) * 2];
                mma_bf16(o[di], pha, vp);
                mma_bf16(o[di], pha, lp);
                mma_bf16(o[di], pla, vp);
            }
        }

        __syncthreads();
        if (kt + 2 < NITER) LOAD_KV(kt & 1, (kt + 2) << 6);
    }

    // ---- epilogue: normalize, split, store ----
    const float inv0 = 1.0f / l0, inv1 = 1.0f / l1;
    const int r0 = q0 + (w << 4) + (l >> 2);
#pragma unroll
    for (int di = 0; di < 8; di++) {
        const int col = h64 + (di << 3) + ((l & 3) << 1);
        uint32_t h0, lo0, h1, lo1;
        split2(o[di][0] * inv0, o[di][1] * inv0, h0, lo0);
        split2(o[di][2] * inv1, o[di][3] * inv1, h1, lo1);
        *(uint32_t*)(Oh + (rowbase + r0) * 1024 + col) = h0;
        *(uint32_t*)(Ol + (rowbase + r0) * 1024 + col) = lo0;
        *(uint32_t*)(Oh + (rowbase + r0 + 8) * 1024 + col) = h1;
        *(uint32_t*)(Ol + (rowbase + r0 + 8) * 1024 + col) = lo1;
    }
}

// ---------------- launch ----------------
extern "C" void kernel_launch(void* const* d_in, const int* in_sizes, int n_in,
                              void* d_out, int out_size)
{
    const float* x     = (const float*)d_in[0];
    const float* w_in  = (const float*)d_in[1];
    const float* b_in  = (const float*)d_in[2];
    const float* w_out = (const float*)d_in[3];
    const float* b_out = (const float*)d_in[4];
    const unsigned char* mask = (const unsigned char*)d_in[5];
    float* out = (float*)d_out;

    __nv_bfloat16 *xh, *xl, *wih, *wil, *woh, *wol, *qkh, *qkl;
    __nv_bfloat16 *qh, *ql, *kh, *kl, *vh, *vl, *cth, *ctl;
    cudaGetSymbolAddress((void**)&xh,  g_xh);  cudaGetSymbolAddress((void**)&xl,  g_xl);
    cudaGetSymbolAddress((void**)&wih, g_wih); cudaGetSymbolAddress((void**)&wil, g_wil);
    cudaGetSymbolAddress((void**)&woh, g_woh); cudaGetSymbolAddress((void**)&wol, g_wol);
    cudaGetSymbolAddress((void**)&qkh, g_qkh); cudaGetSymbolAddress((void**)&qkl, g_qkl);
    cudaGetSymbolAddress((void**)&qh,  g_qh);  cudaGetSymbolAddress((void**)&ql,  g_ql);
    cudaGetSymbolAddress((void**)&kh,  g_kh);  cudaGetSymbolAddress((void**)&kl,  g_kl);
    cudaGetSymbolAddress((void**)&vh,  g_vh);  cudaGetSymbolAddress((void**)&vl,  g_vl);
    cudaGetSymbolAddress((void**)&cth, g_cth); cudaGetSymbolAddress((void**)&ctl, g_ctl);

    cudaFuncSetAttribute(gemm_mma<0>, cudaFuncAttributeMaxDynamicSharedMemorySize, GEMM_SMEM);
    cudaFuncSetAttribute(gemm_mma<1>, cudaFuncAttributeMaxDynamicSharedMemorySize, GEMM_SMEM);
    cudaFuncSetAttribute(gemm_mma<2>, cudaFuncAttributeMaxDynamicSharedMemorySize, GEMM_SMEM);
    cudaFuncSetAttribute(attn_mma,    cudaFuncAttributeMaxDynamicSharedMemorySize, ATT_SMEM);

    // split inputs
    split_kernel<<<8192, 256>>>(x,     xh,  xl,  2097152);
    split_kernel<<<3072, 256>>>(w_in,  wih, wil, 786432);
    split_kernel<<<1024, 256>>>(w_out, woh, wol, 262144);

    // 1) qkv = x @ Win^T + b with fused RoPE + split -> qkh/qkl (8192 x 3072 bf16)
    gemm_mma<2><<<dim3(24, 64), 256, GEMM_SMEM>>>(xh, xl, 1024, wih, wil, 1024,
                                                  b_in, nullptr, qkh, qkl, 1.0f, 3072, 1024);
    // 2) second projection -> bf16 hi/lo (q scaled by 1/sqrt(D))
    gemm_mma<1><<<dim3(8, 64), 256, GEMM_SMEM>>>(qkh,        qkl,        3072, wih,               wil,               1024,
                                                 b_in,        nullptr, qh, ql, 0.125f, 1024, 1024);
    gemm_mma<1><<<dim3(8, 64), 256, GEMM_SMEM>>>(qkh + 1024, qkl + 1024, 3072, wih + 1024 * 1024, wil + 1024 * 1024, 1024,
                                                 b_in + 1024, nullptr, kh, kl, 1.0f,   1024, 1024);
    gemm_mma<1><<<dim3(8, 64), 256, GEMM_SMEM>>>(qkh + 2048, qkl + 2048, 3072, wih + 2048 * 1024, wil + 2048 * 1024, 1024,
                                                 b_in + 2048, nullptr, vh, vl, 1.0f,   1024, 1024);
    // 3) attention (2 CTAs/SM) -> ctx hi/lo
    attn_mma<<<dim3(32, 16, 4), 128, ATT_SMEM>>>(qh, ql, kh, kl, vh, vl, mask, cth, ctl);
    // 4) out = ctx @ Wout^T + b (fp32 out)
    gemm_mma<0><<<dim3(8, 64), 256, GEMM_SMEM>>>(cth, ctl, 1024, woh, wol, 1024,
                                                 b_out, out, nullptr, nullptr, 1.0f, 1024, 1024);
}

// round 11
// speedup vs baseline: 3.3617x; 1.1397x over previous
#include <cuda_runtime.h>
#include <cuda_bf16.h>
#include <math.h>
#include <stdint.h>

#define E_DIM 1024
#define S_LEN 2048

// ---------------- scratch (no allocation allowed) ----------------
__device__ __nv_bfloat16 g_xh [8388608],  g_xl [8388608];
__device__ __nv_bfloat16 g_wih[3145728],  g_wil[3145728];
__device__ __nv_bfloat16 g_woh[1048576],  g_wol[1048576];
__device__ __nv_bfloat16 g_qkh[25165824], g_qkl[25165824];  // rope'd qkv hi/lo
__device__ __nv_bfloat16 g_qh [8388608],  g_ql [8388608];   // q2 hi/lo (scaled 0.125)
__device__ __nv_bfloat16 g_kh [8388608],  g_kl [8388608];
__device__ __nv_bfloat16 g_vh [8388608],  g_vl [8388608];
__device__ __nv_bfloat16 g_cth[8388608],  g_ctl[8388608];   // ctx hi/lo

// ---------------- helpers ----------------
__device__ __forceinline__ uint32_t smem_u32(const void* p) {
    uint32_t a;
    asm("{ .reg .u64 t; cvta.to.shared.u64 t, %1; cvt.u32.u64 %0, t; }" : "=r"(a) : "l"(p));
    return a;
}
__device__ __forceinline__ void cp16(uint32_t s, const void* g) {
    asm volatile("cp.async.cg.shared.global [%0], [%1], 16;" :: "r"(s), "l"(g));
}
__device__ __forceinline__ void ldsm4(uint32_t* r, uint32_t a) {
    asm volatile("ldmatrix.sync.aligned.m8n8.x4.shared.b16 {%0,%1,%2,%3}, [%4];"
        : "=r"(r[0]), "=r"(r[1]), "=r"(r[2]), "=r"(r[3]) : "r"(a));
}
__device__ __forceinline__ void ldsm4t(uint32_t* r, uint32_t a) {
    asm volatile("ldmatrix.sync.aligned.m8n8.x4.trans.shared.b16 {%0,%1,%2,%3}, [%4];"
        : "=r"(r[0]), "=r"(r[1]), "=r"(r[2]), "=r"(r[3]) : "r"(a));
}
__device__ __forceinline__ void mma_bf16(float* c, const uint32_t* a, const uint32_t* b) {
    asm volatile("mma.sync.aligned.m16n8k16.row.col.f32.bf16.bf16.f32 "
        "{%0,%1,%2,%3}, {%4,%5,%6,%7}, {%8,%9}, {%0,%1,%2,%3};"
        : "+f"(c[0]), "+f"(c[1]), "+f"(c[2]), "+f"(c[3])
        : "r"(a[0]), "r"(a[1]), "r"(a[2]), "r"(a[3]), "r"(b[0]), "r"(b[1]));
}
__device__ __forceinline__ uint32_t pack2(__nv_bfloat16 a, __nv_bfloat16 b) {
    unsigned short ua = *(unsigned short*)&a, ub = *(unsigned short*)&b;
    return (uint32_t)ua | ((uint32_t)ub << 16);
}
__device__ __forceinline__ void split2(float x, float y, uint32_t& hi, uint32_t& lo) {
    __nv_bfloat16 hx = __float2bfloat16_rn(x);
    __nv_bfloat16 hy = __float2bfloat16_rn(y);
    __nv_bfloat16 lx = __float2bfloat16_rn(x - __bfloat162float(hx));
    __nv_bfloat16 ly = __float2bfloat16_rn(y - __bfloat162float(hy));
    hi = pack2(hx, hy); lo = pack2(lx, ly);
}

// ---------------- split fp32 -> bf16 hi + bf16 lo ----------------
__global__ void split_kernel(const float* __restrict__ src,
                             __nv_bfloat16* __restrict__ hi,
                             __nv_bfloat16* __restrict__ lo, int n4)
{
    int q = blockIdx.x * 256 + threadIdx.x;
    if (q >= n4) return;
    int i = q << 2;
    float4 v = *(const float4*)(src + i);
    float f[4] = {v.x, v.y, v.z, v.w};
    __nv_bfloat16 h[4], l[4];
#pragma unroll
    for (int j = 0; j < 4; j++) {
        h[j] = __float2bfloat16_rn(f[j]);
        l[j] = __float2bfloat16_rn(f[j] - __bfloat162float(h[j]));
    }
    *(__nv_bfloat162*)(hi + i)     = __nv_bfloat162(h[0], h[1]);
    *(__nv_bfloat162*)(hi + i + 2) = __nv_bfloat162(h[2], h[3]);
    *(__nv_bfloat162*)(lo + i)     = __nv_bfloat162(l[0], l[1]);
    *(__nv_bfloat162*)(lo + i + 2) = __nv_bfloat162(l[2], l[3]);
}

// ---------------- mma.sync bf16x2 GEMM: C[M,N] = A[M,K] @ B[N,K]^T + bias ----------------
// OM=0: fp32 out.
// OM=2: RoPE (N-tiles 0..15) + bf16 hi/lo out  [GEMM1 fused epilogue]
// OM=3: merged q2/k2/v2: seg = blockIdx.x>>3 selects A col-slice + routed bf16 hi/lo out
#define OPB       8192
#define STGB      (4 * OPB)
#define GEMM_SMEM (3 * STGB)

__device__ __forceinline__ void issue_stage(uint32_t sb, int stg, int k0,
    const __nv_bfloat16* Ahb, const __nv_bfloat16* Alb,
    const __nv_bfloat16* Bhb, const __nv_bfloat16* Blb,
    int lda, int ldb, int lr, int lr1, int lkc, uint32_t so0, uint32_t so1)
{
    uint32_t s = sb + (uint32_t)stg * STGB;
    const int kb8 = k0 + lkc * 8;
    cp16(s +           so0, Ahb + (size_t)lr  * lda + kb8);
    cp16(s +           so1, Ahb + (size_t)lr1 * lda + kb8);
    cp16(s + OPB +     so0, Alb + (size_t)lr  * lda + kb8);
    cp16(s + OPB +     so1, Alb + (size_t)lr1 * lda + kb8);
    cp16(s + 2 * OPB + so0, Bhb + (size_t)lr  * ldb + kb8);
    cp16(s + 2 * OPB + so1, Bhb + (size_t)lr1 * ldb + kb8);
    cp16(s + 3 * OPB + so0, Blb + (size_t)lr  * ldb + kb8);
    cp16(s + 3 * OPB + so1, Blb + (size_t)lr1 * ldb + kb8);
    asm volatile("cp.async.commit_group;" ::: "memory");
}

template<int OM>
__global__ __launch_bounds__(256, 2)
void gemm_mma(const __nv_bfloat16* __restrict__ Ah, const __nv_bfloat16* __restrict__ Al, int lda,
              const __nv_bfloat16* __restrict__ Bh, const __nv_bfloat16* __restrict__ Bl, int ldb,
              const float* __restrict__ bias, float* __restrict__ C,
              __nv_bfloat16* __restrict__ Ch, __nv_bfloat16* __restrict__ Cl,
              float scale, int ldc, int K)
{
    extern __shared__ char smraw[];
    const uint32_t sb = smem_u32(smraw);
    const int tid = threadIdx.x;
    const int l = tid & 31, w = tid >> 5;
    const int wm = (w >> 2) * 64, wn = (w & 3) * 32;
    const int mb = blockIdx.y * 128, nb = blockIdx.x * 128;
    const int seg = (OM == 3) ? (blockIdx.x >> 3) : 0;
    const int aoff = (OM == 3) ? (seg << 10) : 0;

    const __nv_bfloat16* Ahb = Ah + (size_t)mb * lda + aoff;
    const __nv_bfloat16* Alb = Al + (size_t)mb * lda + aoff;
    const __nv_bfloat16* Bhb = Bh + (size_t)nb * ldb;
    const __nv_bfloat16* Blb = Bl + (size_t)nb * ldb;

    const int lr  = tid >> 2;
    const int lr1 = lr + 64;
    const int lkc = tid & 3;
    const uint32_t so0 = (uint32_t)(lr  * 64 + ((lkc ^ ((lr  >> 1) & 3)) << 4));
    const uint32_t so1 = (uint32_t)(lr1 * 64 + ((lkc ^ ((lr1 >> 1) & 3)) << 4));

    const int rA = l & 15, kselA = l >> 4, swA = (rA >> 1) & 3;
    const uint32_t aRow = (uint32_t)((wm + rA) * 64);
    const uint32_t aK0 = (uint32_t)(((0 + kselA) ^ swA) << 4);
    const uint32_t aK1 = (uint32_t)(((2 + kselA) ^ swA) << 4);
    const int rB = (l & 7) + ((l >> 4) << 3), kselB = (l >> 3) & 1, swB = (rB >> 1) & 3;
    const uint32_t bRow = (uint32_t)((wn + rB) * 64);
    const uint32_t bK0 = (uint32_t)(((0 + kselB) ^ swB) << 4);
    const uint32_t bK1 = (uint32_t)(((2 + kselB) ^ swB) << 4);

    float acc[4][4][4];
#pragma unroll
    for (int mi = 0; mi < 4; mi++)
#pragma unroll
        for (int ni = 0; ni < 4; ni++)
#pragma unroll
            for (int i = 0; i < 4; i++) acc[mi][ni][i] = 0.0f;

    const int NKB = K >> 5;
    issue_stage(sb, 0, 0,  Ahb, Alb, Bhb, Blb, lda, ldb, lr, lr1, lkc, so0, so1);
    issue_stage(sb, 1, 32, Ahb, Alb, Bhb, Blb, lda, ldb, lr, lr1, lkc, so0, so1);

    for (int kb = 0; kb < NKB; kb++) {
        if (kb < NKB - 2) asm volatile("cp.async.wait_group 1;" ::: "memory");
        else              asm volatile("cp.async.wait_group 0;" ::: "memory");
        __syncthreads();
        if (kb + 2 < NKB)
            issue_stage(sb, (kb + 2) % 3, (kb + 2) * 32,
                        Ahb, Alb, Bhb, Blb, lda, ldb, lr, lr1, lkc, so0, so1);

        const uint32_t s = sb + (uint32_t)(kb % 3) * STGB;
        // register-lean: full A-frag set (32 regs), one B hi/lo pair (8 regs) at a time
#pragma unroll
        for (int kk = 0; kk < 2; kk++) {
            const uint32_t aK = kk ? aK1 : aK0;
            const uint32_t bK = kk ? bK1 : bK0;
            uint32_t ah[4][4], al4[4][4];
#pragma unroll
            for (int mi = 0; mi < 4; mi++) {
                ldsm4(ah[mi],  s +       aRow + mi * 1024 + aK);
                ldsm4(al4[mi], s + OPB + aRow + mi * 1024 + aK);
            }
#pragma unroll
            for (int g = 0; g < 2; g++) {
                uint32_t bh[4], bl[4];
                ldsm4(bh, s + 2 * OPB + bRow + g * 1024 + bK);
                ldsm4(bl, s + 3 * OPB + bRow + g * 1024 + bK);
#pragma unroll
                for (int mi = 0; mi < 4; mi++)
#pragma unroll
                    for (int nk = 0; nk < 2; nk++) {
                        float* c = acc[mi][g * 2 + nk];
                        mma_bf16(c, ah[mi],  &bh[nk * 2]);
                        mma_bf16(c, ah[mi],  &bl[nk * 2]);
                        mma_bf16(c, al4[mi], &bh[nk * 2]);
                    }
            }
        }
    }

    const int cr = l >> 2, cc2 = (l & 3) * 2;

    if (OM == 2) {
        // ---- fused RoPE + split epilogue (GEMM1) ----
        __syncthreads();                       // mainloop smem reads done
        float* sE = (float*)smraw;             // 128 x 132 fp32 staging (67.6KB <= 96KB)
#pragma unroll
        for (int ni = 0; ni < 4; ni++) {
            const int colg = nb + wn + ni * 8 + cc2;
            const float b0 = bias[colg], b1 = bias[colg + 1];
            const int colL = wn + ni * 8 + cc2;
#pragma unroll
            for (int mi = 0; mi < 4; mi++) {
                const int rowL = wm + mi * 16 + cr;
                sE[rowL * 132 + colL]           = acc[mi][ni][0] + b0;
                sE[rowL * 132 + colL + 1]       = acc[mi][ni][1] + b1;
                sE[(rowL + 8) * 132 + colL]     = acc[mi][ni][2] + b0;
                sE[(rowL + 8) * 132 + colL + 1] = acc[mi][ni][3] + b1;
            }
        }
        __syncthreads();
        const bool doRope = (blockIdx.x < 16);      // q,k tiles; v tiles pass through
        const int i0 = (tid & 15) << 1;
        const int hh = (tid >> 4) & 1;
        const int rb0 = tid >> 5;
        const float invA = (float)exp2(-(double)i0 * 0.41524101186091903);
        const float invB = (float)exp2(-(double)(i0 + 1) * 0.41524101186091903);
        const int colL = hh * 64 + i0;
#pragma unroll 4
        for (int rr = 0; rr < 16; rr++) {
            const int row = rb0 + (rr << 3);
            float cA = 1.0f, sA = 0.0f, cB = 1.0f, sB = 0.0f;
            if (doRope) {
                const float sPos = (float)((mb + row) & (S_LEN - 1));
                sincosf(sPos * invA, &sA, &cA);
                sincosf(sPos * invB, &sB, &cB);
            }
            float2 x0 = *(float2*)&sE[row * 132 + colL];
            float2 x1 = *(float2*)&sE[row * 132 + colL + 32];
            float r00 = x0.x * cA - x1.x * sA, r01 = x0.y * cB - x1.y * sB;
            float r10 = x1.x * cA + x0.x * sA, r11 = x1.y * cB + x0.y * sB;
            uint32_t h0, l0, h1, l1;
            split2(r00, r01, h0, l0);
            split2(r10, r11, h1, l1);
            const size_t base = (size_t)(mb + row) * ldc + nb + colL;
            *(uint32_t*)(Ch + base)      = h0;
            *(uint32_t*)(Cl + base)      = l0;
            *(uint32_t*)(Ch + base + 32) = h1;
            *(uint32_t*)(Cl + base + 32) = l1;
        }
        return;
    }

    if (OM == 3) {
        // ---- merged q2/k2/v2 epilogue: route by segment ----
        __nv_bfloat16* Coh = (seg == 0) ? g_qh : (seg == 1) ? g_kh : g_vh;
        __nv_bfloat16* Col = (seg == 0) ? g_ql : (seg == 1) ? g_kl : g_vl;
        const float sc = (seg == 0) ? 0.125f : 1.0f;
        const int nbo = nb - (seg << 10);
#pragma unroll
        for (int ni = 0; ni < 4; ni++) {
            const int colg = nb + wn + ni * 8 + cc2;
            const float b0 = bias[colg], b1 = bias[colg + 1];
            const int col = nbo + wn + ni * 8 + cc2;
#pragma unroll
            for (int mi = 0; mi < 4; mi++) {
                const int row = mb + wm + mi * 16 + cr;
                float v0 = (acc[mi][ni][0] + b0) * sc, v1 = (acc[mi][ni][1] + b1) * sc;
                float v2 = (acc[mi][ni][2] + b0) * sc, v3 = (acc[mi][ni][3] + b1) * sc;
                uint32_t h0, l0, h1, l1;
                split2(v0, v1, h0, l0);
                split2(v2, v3, h1, l1);
                *(uint32_t*)(Coh + (size_t)row * 1024 + col) = h0;
                *(uint32_t*)(Col + (size_t)row * 1024 + col) = l0;
                *(uint32_t*)(Coh + (size_t)(row + 8) * 1024 + col) = h1;
                *(uint32_t*)(Col + (size_t)(row + 8) * 1024 + col) = l1;
            }
        }
        return;
    }

    // OM == 0: fp32 out
#pragma unroll
    for (int ni = 0; ni < 4; ni++) {
        const int col = nb + wn + ni * 8 + cc2;
        const float b0 = bias[col], b1 = bias[col + 1];
#pragma unroll
        for (int mi = 0; mi < 4; mi++) {
            const int row = mb + wm + mi * 16 + cr;
            *(float2*)(C + (size_t)row * ldc + col) =
                make_float2(acc[mi][ni][0] + b0, acc[mi][ni][1] + b1);
            *(float2*)(C + (size_t)(row + 8) * ldc + col) =
                make_float2(acc[mi][ni][2] + b0, acc[mi][ni][3] + b1);
        }
    }
}

// ---------------- Flash attention on mma.sync bf16x2 (R10 proven) ----------------
#define ATT_QL   8192
#define ATT_MASK 16384
#define ATT_KV   18432
#define ATT_STG  32768
#define ATT_SMEM (ATT_KV + 2 * ATT_STG)   // 83968
#define NITER    32

__global__ __launch_bounds__(128, 2)
void attn_mma(const __nv_bfloat16* __restrict__ qh, const __nv_bfloat16* __restrict__ ql,
              const __nv_bfloat16* __restrict__ kh, const __nv_bfloat16* __restrict__ kl,
              const __nv_bfloat16* __restrict__ vh, const __nv_bfloat16* __restrict__ vl,
              const unsigned char* __restrict__ maskg,
              __nv_bfloat16* __restrict__ Oh, __nv_bfloat16* __restrict__ Ol)
{
    extern __shared__ char sm[];
    const uint32_t sb = smem_u32(sm);
    const int tid = threadIdx.x, l = tid & 31, w = tid >> 5;
    const int b = blockIdx.z, h = blockIdx.y, q0 = blockIdx.x << 6;
    const size_t rowbase = (size_t)b * S_LEN;
    const int h64 = h << 6;

    {
        const int tile = tid >> 6;
        const __nv_bfloat16* src = tile ? ql : qh;
        const uint32_t dstb = sb + tile * ATT_QL;
        const int base = tid & 63;
#pragma unroll
        for (int i = 0; i < 8; i++) {
            int idx = base + i * 64; int r = idx >> 3, c = idx & 7;
            cp16(dstb + r * 128 + ((c ^ (r & 7)) << 4),
                 src + (rowbase + q0 + r) * 1024 + h64 + c * 8);
        }
        cp16(sb + ATT_MASK + tid * 16, maskg + (size_t)b * S_LEN + tid * 16);
    }
    const int kvtile = tid >> 5;
    const __nv_bfloat16* kvsrc = (kvtile == 0) ? kh : (kvtile == 1) ? kl : (kvtile == 2) ? vh : vl;
    const int kvbase = tid & 31;
#define LOAD_KV(stg, kb) do {                                                     \
        uint32_t dstb = sb + ATT_KV + (stg) * ATT_STG + kvtile * 8192;            \
        _Pragma("unroll")                                                         \
        for (int i = 0; i < 16; i++) {                                            \
            int idx = kvbase + i * 32; int r = idx >> 3, c = idx & 7;             \
            cp16(dstb + r * 128 + ((c ^ (r & 7)) << 4),                           \
                 kvsrc + (rowbase + (kb) + r) * 1024 + h64 + c * 8);              \
        }                                                                         \
        asm volatile("cp.async.commit_group;" ::: "memory");                      \
    } while (0)

    LOAD_KV(0, 0);
    LOAD_KV(1, 64);

    asm volatile("cp.async.wait_group 1;" ::: "memory");
    __syncthreads();

    uint32_t qfh[4][4], qfl[4][4];
    {
        int row = (w << 4) + (l & 15);
#pragma unroll
        for (int j = 0; j < 4; j++) {
            uint32_t ch = (uint32_t)(((2 * j + (l >> 4)) ^ (row & 7)) << 4);
            ldsm4(qfh[j], sb +          row * 128 + ch);
            ldsm4(qfl[j], sb + ATT_QL + row * 128 + ch);
        }
    }

    float o[8][4];
#pragma unroll
    for (int di = 0; di < 8; di++)
#pragma unroll
        for (int i = 0; i < 4; i++) o[di][i] = 0.0f;
    float m0 = -1e30f, m1 = -1e30f, l0 = 0.0f, l1 = 0.0f;

    const unsigned char* Ms = (const unsigned char*)sm + ATT_MASK;

    for (int kt = 0; kt < NITER; kt++) {
        if (kt > 0) {
            if (kt < 30) asm volatile("cp.async.wait_group 1;" ::: "memory");
            else         asm volatile("cp.async.wait_group 0;" ::: "memory");
            __syncthreads();
        }
        const uint32_t stg = sb + ATT_KV + (uint32_t)(kt & 1) * ATT_STG;
        const int kb = kt << 6;

        float S[8][4];
#pragma unroll
        for (int ni = 0; ni < 8; ni++)
#pragma unroll
            for (int i = 0; i < 4; i++) S[ni][i] = 0.0f;

#pragma unroll
        for (int j = 0; j < 4; j++) {
            uint32_t bh4[4][4], bl4[4][4];
#pragma unroll
            for (int ng = 0; ng < 4; ng++) {
                int row = (ng << 4) + (l & 7) + ((l >> 4) << 3);
                uint32_t ch = (uint32_t)(((2 * j + ((l >> 3) & 1)) ^ (row & 7)) << 4);
                ldsm4(bh4[ng], stg +        row * 128 + ch);
                ldsm4(bl4[ng], stg + 8192 + row * 128 + ch);
            }
#pragma unroll
            for (int ni = 0; ni < 8; ni++) {
                uint32_t* bp = &bh4[ni >> 1][(ni & 1) * 2];
                uint32_t* lp = &bl4[ni >> 1][(ni & 1) * 2];
                mma_bf16(S[ni], qfh[j], bp);
                mma_bf16(S[ni], qfh[j], lp);
                mma_bf16(S[ni], qfl[j], bp);
            }
        }

        float tm0 = -1e30f, tm1 = -1e30f;
#pragma unroll
        for (int ni = 0; ni < 8; ni++) {
            uchar2 mm = *(const uchar2*)(Ms + kb + (ni << 3) + ((l & 3) << 1));
            if (mm.x) { S[ni][0] = -1e30f; S[ni][2] = -1e30f; }
            if (mm.y) { S[ni][1] = -1e30f; S[ni][3] = -1e30f; }
            tm0 = fmaxf(tm0, fmaxf(S[ni][0], S[ni][1]));
            tm1 = fmaxf(tm1, fmaxf(S[ni][2], S[ni][3]));
        }
        tm0 = fmaxf(tm0, __shfl_xor_sync(0xffffffffu, tm0, 1));
        tm0 = fmaxf(tm0, __shfl_xor_sync(0xffffffffu, tm0, 2));
        tm1 = fmaxf(tm1, __shfl_xor_sync(0xffffffffu, tm1, 1));
        tm1 = fmaxf(tm1, __shfl_xor_sync(0xffffffffu, tm1, 2));
        float mn0 = fmaxf(m0, tm0), mn1 = fmaxf(m1, tm1);
        float c0 = __expf(m0 - mn0), c1 = __expf(m1 - mn1);
        m0 = mn0; m1 = mn1;
        float rs0 = 0.0f, rs1 = 0.0f;
#pragma unroll
        for (int ni = 0; ni < 8; ni++) {
            S[ni][0] = __expf(S[ni][0] - mn0); rs0 += S[ni][0];
            S[ni][1] = __expf(S[ni][1] - mn0); rs0 += S[ni][1];
            S[ni][2] = __expf(S[ni][2] - mn1); rs1 += S[ni][2];
            S[ni][3] = __expf(S[ni][3] - mn1); rs1 += S[ni][3];
        }
        rs0 += __shfl_xor_sync(0xffffffffu, rs0, 1);
        rs0 += __shfl_xor_sync(0xffffffffu, rs0, 2);
        rs1 += __shfl_xor_sync(0xffffffffu, rs1, 1);
        rs1 += __shfl_xor_sync(0xffffffffu, rs1, 2);
        l0 = l0 * c0 + rs0; l1 = l1 * c1 + rs1;
#pragma unroll
        for (int di = 0; di < 8; di++) {
            o[di][0] *= c0; o[di][1] *= c0; o[di][2] *= c1; o[di][3] *= c1;
        }

#pragma unroll
        for (int js = 0; js < 4; js++) {
            uint32_t pha[4], pla[4];
            {
                const int t0 = 2 * js, t1 = t0 + 1;
                split2(S[t0][0], S[t0][1], pha[0], pla[0]);
                split2(S[t0][2], S[t0][3], pha[1], pla[1]);
                split2(S[t1][0], S[t1][1], pha[2], pla[2]);
                split2(S[t1][2], S[t1][3], pha[3], pla[3]);
            }
            uint32_t vh4[4][4], vl4[4][4];
#pragma unroll
            for (int dg = 0; dg < 4; dg++) {
                int row = (js << 4) + (l & 7) + (((l >> 3) & 1) << 3);
                uint32_t ch = (uint32_t)(((2 * dg + (l >> 4)) ^ (row & 7)) << 4);
                ldsm4t(vh4[dg], stg + 16384 + row * 128 + ch);
                ldsm4t(vl4[dg], stg + 24576 + row * 128 + ch);
            }
#pragma unroll
            for (int di = 0; di < 8; di++) {
                uint32_t* vp = &vh4[di >> 1][(di & 1) * 2];
                uint32_t* lp = &vl4[di >> 1][(di & 1) * 2];
                mma_bf16(o[di], pha, vp);
                mma_bf16(o[di], pha, lp);
                mma_bf16(o[di], pla, vp);
            }
        }

        __syncthreads();
        if (kt + 2 < NITER) LOAD_KV(kt & 1, (kt + 2) << 6);
    }

    const float inv0 = 1.0f / l0, inv1 = 1.0f / l1;
    const int r0 = q0 + (w << 4) + (l >> 2);
#pragma unroll
    for (int di = 0; di < 8; di++) {
        const int col = h64 + (di << 3) + ((l & 3) << 1);
        uint32_t h0, lo0, h1, lo1;
        split2(o[di][0] * inv0, o[di][1] * inv0, h0, lo0);
        split2(o[di][2] * inv1, o[di][3] * inv1, h1, lo1);
        *(uint32_t*)(Oh + (rowbase + r0) * 1024 + col) = h0;
        *(uint32_t*)(Ol + (rowbase + r0) * 1024 + col) = lo0;
        *(uint32_t*)(Oh + (rowbase + r0 + 8) * 1024 + col) = h1;
        *(uint32_t*)(Ol + (rowbase + r0 + 8) * 1024 + col) = lo1;
    }
}

// ---------------- launch ----------------
extern "C" void kernel_launch(void* const* d_in, const int* in_sizes, int n_in,
                              void* d_out, int out_size)
{
    const float* x     = (const float*)d_in[0];
    const float* w_in  = (const float*)d_in[1];
    const float* b_in  = (const float*)d_in[2];
    const float* w_out = (const float*)d_in[3];
    const float* b_out = (const float*)d_in[4];
    const unsigned char* mask = (const unsigned char*)d_in[5];
    float* out = (float*)d_out;

    __nv_bfloat16 *xh, *xl, *wih, *wil, *woh, *wol, *qkh, *qkl;
    __nv_bfloat16 *qh, *ql, *kh, *kl, *vh, *vl, *cth, *ctl;
    cudaGetSymbolAddress((void**)&xh,  g_xh);  cudaGetSymbolAddress((void**)&xl,  g_xl);
    cudaGetSymbolAddress((void**)&wih, g_wih); cudaGetSymbolAddress((void**)&wil, g_wil);
    cudaGetSymbolAddress((void**)&woh, g_woh); cudaGetSymbolAddress((void**)&wol, g_wol);
    cudaGetSymbolAddress((void**)&qkh, g_qkh); cudaGetSymbolAddress((void**)&qkl, g_qkl);
    cudaGetSymbolAddress((void**)&qh,  g_qh);  cudaGetSymbolAddress((void**)&ql,  g_ql);
    cudaGetSymbolAddress((void**)&kh,  g_kh);  cudaGetSymbolAddress((void**)&kl,  g_kl);
    cudaGetSymbolAddress((void**)&vh,  g_vh);  cudaGetSymbolAddress((void**)&vl,  g_vl);
    cudaGetSymbolAddress((void**)&cth, g_cth); cudaGetSymbolAddress((void**)&ctl, g_ctl);

    cudaFuncSetAttribute(gemm_mma<0>, cudaFuncAttributeMaxDynamicSharedMemorySize, GEMM_SMEM);
    cudaFuncSetAttribute(gemm_mma<2>, cudaFuncAttributeMaxDynamicSharedMemorySize, GEMM_SMEM);
    cudaFuncSetAttribute(gemm_mma<3>, cudaFuncAttributeMaxDynamicSharedMemorySize, GEMM_SMEM);
    cudaFuncSetAttribute(attn_mma,    cudaFuncAttributeMaxDynamicSharedMemorySize, ATT_SMEM);

    // split inputs
    split_kernel<<<8192, 256>>>(x,     xh,  xl,  2097152);
    split_kernel<<<3072, 256>>>(w_in,  wih, wil, 786432);
    split_kernel<<<1024, 256>>>(w_out, woh, wol, 262144);

    // 1) qkv = x @ Win^T + b with fused RoPE + split -> qkh/qkl (8192 x 3072 bf16)
    gemm_mma<2><<<dim3(24, 64), 256, GEMM_SMEM>>>(xh, xl, 1024, wih, wil, 1024,
                                                  b_in, nullptr, qkh, qkl, 1.0f, 3072, 1024);
    // 2) merged second projection: one launch, outputs routed to qh/ql, kh/kl, vh/vl
    gemm_mma<3><<<dim3(24, 64), 256, GEMM_SMEM>>>(qkh, qkl, 3072, wih, wil, 1024,
                                                  b_in, nullptr, nullptr, nullptr, 1.0f, 1024, 1024);
    // 3) attention (2 CTAs/SM) -> ctx hi/lo
    attn_mma<<<dim3(32, 16, 4), 128, ATT_SMEM>>>(qh, ql, kh, kl, vh, vl, mask, cth, ctl);
    // 4) out = ctx @ Wout^T + b (fp32 out)
    gemm_mma<0><<<dim3(8, 64), 256, GEMM_SMEM>>>(cth, ctl, 1024, woh, wol, 1024,
                                                 b_out, out, nullptr, nullptr, 1.0f, 1024, 1024);
}

// round 12
// speedup vs baseline: 3.4708x; 1.0325x over previous
#include <cuda_runtime.h>
#include <cuda_bf16.h>
#include <math.h>
#include <stdint.h>

#define E_DIM 1024
#define S_LEN 2048

// ---------------- scratch (no allocation allowed) ----------------
__device__ __nv_bfloat16 g_xh [8388608],  g_xl [8388608];
__device__ __nv_bfloat16 g_wih[3145728],  g_wil[3145728];
__device__ __nv_bfloat16 g_woh[1048576],  g_wol[1048576];
__device__ __nv_bfloat16 g_qkh[25165824], g_qkl[25165824];  // rope'd qkv hi/lo
__device__ __nv_bfloat16 g_qh [8388608],  g_ql [8388608];   // q2 hi/lo (scaled 0.125)
__device__ __nv_bfloat16 g_kh [8388608],  g_kl [8388608];
__device__ __nv_bfloat16 g_vh [8388608],  g_vl [8388608];
__device__ __nv_bfloat16 g_cth[8388608],  g_ctl[8388608];   // ctx hi/lo

// ---------------- helpers ----------------
__device__ __forceinline__ uint32_t smem_u32(const void* p) {
    uint32_t a;
    asm("{ .reg .u64 t; cvta.to.shared.u64 t, %1; cvt.u32.u64 %0, t; }" : "=r"(a) : "l"(p));
    return a;
}
__device__ __forceinline__ void cp16(uint32_t s, const void* g) {
    asm volatile("cp.async.cg.shared.global [%0], [%1], 16;" :: "r"(s), "l"(g));
}
__device__ __forceinline__ void ldsm4(uint32_t* r, uint32_t a) {
    asm volatile("ldmatrix.sync.aligned.m8n8.x4.shared.b16 {%0,%1,%2,%3}, [%4];"
        : "=r"(r[0]), "=r"(r[1]), "=r"(r[2]), "=r"(r[3]) : "r"(a));
}
__device__ __forceinline__ void ldsm4t(uint32_t* r, uint32_t a) {
    asm volatile("ldmatrix.sync.aligned.m8n8.x4.trans.shared.b16 {%0,%1,%2,%3}, [%4];"
        : "=r"(r[0]), "=r"(r[1]), "=r"(r[2]), "=r"(r[3]) : "r"(a));
}
__device__ __forceinline__ void mma_bf16(float* c, const uint32_t* a, const uint32_t* b) {
    asm volatile("mma.sync.aligned.m16n8k16.row.col.f32.bf16.bf16.f32 "
        "{%0,%1,%2,%3}, {%4,%5,%6,%7}, {%8,%9}, {%0,%1,%2,%3};"
        : "+f"(c[0]), "+f"(c[1]), "+f"(c[2]), "+f"(c[3])
        : "r"(a[0]), "r"(a[1]), "r"(a[2]), "r"(a[3]), "r"(b[0]), "r"(b[1]));
}
__device__ __forceinline__ uint32_t pack2(__nv_bfloat16 a, __nv_bfloat16 b) {
    unsigned short ua = *(unsigned short*)&a, ub = *(unsigned short*)&b;
    return (uint32_t)ua | ((uint32_t)ub << 16);
}
__device__ __forceinline__ void split2(float x, float y, uint32_t& hi, uint32_t& lo) {
    __nv_bfloat16 hx = __float2bfloat16_rn(x);
    __nv_bfloat16 hy = __float2bfloat16_rn(y);
    __nv_bfloat16 lx = __float2bfloat16_rn(x - __bfloat162float(hx));
    __nv_bfloat16 ly = __float2bfloat16_rn(y - __bfloat162float(hy));
    hi = pack2(hx, hy); lo = pack2(lx, ly);
}

// ---------------- split fp32 -> bf16 hi + bf16 lo ----------------
__global__ void split_kernel(const float* __restrict__ src,
                             __nv_bfloat16* __restrict__ hi,
                             __nv_bfloat16* __restrict__ lo, int n4)
{
    int q = blockIdx.x * 256 + threadIdx.x;
    if (q >= n4) return;
    int i = q << 2;
    float4 v = *(const float4*)(src + i);
    float f[4] = {v.x, v.y, v.z, v.w};
    __nv_bfloat16 h[4], l[4];
#pragma unroll
    for (int j = 0; j < 4; j++) {
        h[j] = __float2bfloat16_rn(f[j]);
        l[j] = __float2bfloat16_rn(f[j] - __bfloat162float(h[j]));
    }
    *(__nv_bfloat162*)(hi + i)     = __nv_bfloat162(h[0], h[1]);
    *(__nv_bfloat162*)(hi + i + 2) = __nv_bfloat162(h[2], h[3]);
    *(__nv_bfloat162*)(lo + i)     = __nv_bfloat162(l[0], l[1]);
    *(__nv_bfloat162*)(lo + i + 2) = __nv_bfloat162(l[2], l[3]);
}

// ---------------- mma.sync bf16x2 GEMM: C[M,N] = A[M,K] @ B[N,K]^T + bias ----------------
// 128 threads, 4 warps, warp tile 64x64 (2x2 warp grid), CTA 128x128, 3-stage pipeline.
// OM=0: fp32 out.
// OM=2: RoPE (N-tiles 0..15) + bf16 hi/lo out  [GEMM1 fused epilogue]
// OM=3: merged q2/k2/v2: seg = blockIdx.x>>3 selects A col-slice + routed bf16 hi/lo out
#define OPB       8192
#define STGB      (4 * OPB)
#define GEMM_SMEM (3 * STGB)

__device__ __forceinline__ void issue_stage(uint32_t sb, int stg, int k0,
    const __nv_bfloat16* Ahb, const __nv_bfloat16* Alb,
    const __nv_bfloat16* Bhb, const __nv_bfloat16* Blb,
    int lda, int ldb, int tid)
{
    uint32_t s = sb + (uint32_t)stg * STGB;
    const int c = tid & 3;
    const int r0 = tid >> 2;               // 0..31
    const int kb8 = k0 + c * 8;
#pragma unroll
    for (int i = 0; i < 4; i++) {
        const int r = r0 + i * 32;
        const uint32_t so = (uint32_t)(r * 64 + ((c ^ ((r >> 1) & 3)) << 4));
        cp16(s +           so, Ahb + (size_t)r * lda + kb8);
        cp16(s + OPB +     so, Alb + (size_t)r * lda + kb8);
        cp16(s + 2 * OPB + so, Bhb + (size_t)r * ldb + kb8);
        cp16(s + 3 * OPB + so, Blb + (size_t)r * ldb + kb8);
    }
    asm volatile("cp.async.commit_group;" ::: "memory");
}

template<int OM>
__global__ __launch_bounds__(128, 2)
void gemm_mma(const __nv_bfloat16* __restrict__ Ah, const __nv_bfloat16* __restrict__ Al, int lda,
              const __nv_bfloat16* __restrict__ Bh, const __nv_bfloat16* __restrict__ Bl, int ldb,
              const float* __restrict__ bias, float* __restrict__ C,
              __nv_bfloat16* __restrict__ Ch, __nv_bfloat16* __restrict__ Cl,
              float scale, int ldc, int K)
{
    extern __shared__ char smraw[];
    const uint32_t sb = smem_u32(smraw);
    const int tid = threadIdx.x;
    const int l = tid & 31, w = tid >> 5;
    const int wm = (w >> 1) * 64, wn = (w & 1) * 64;
    const int mb = blockIdx.y * 128, nb = blockIdx.x * 128;
    const int seg = (OM == 3) ? (blockIdx.x >> 3) : 0;
    const int aoff = (OM == 3) ? (seg << 10) : 0;

    const __nv_bfloat16* Ahb = Ah + (size_t)mb * lda + aoff;
    const __nv_bfloat16* Alb = Al + (size_t)mb * lda + aoff;
    const __nv_bfloat16* Bhb = Bh + (size_t)nb * ldb;
    const __nv_bfloat16* Blb = Bl + (size_t)nb * ldb;

    const int rA = l & 15, kselA = l >> 4, swA = (rA >> 1) & 3;
    const uint32_t aRow = (uint32_t)((wm + rA) * 64);
    const uint32_t aK0 = (uint32_t)(((0 + kselA) ^ swA) << 4);
    const uint32_t aK1 = (uint32_t)(((2 + kselA) ^ swA) << 4);
    const int rB = (l & 7) + ((l >> 4) << 3), kselB = (l >> 3) & 1, swB = (rB >> 1) & 3;
    const uint32_t bRow = (uint32_t)((wn + rB) * 64);
    const uint32_t bK0 = (uint32_t)(((0 + kselB) ^ swB) << 4);
    const uint32_t bK1 = (uint32_t)(((2 + kselB) ^ swB) << 4);

    float acc[4][8][4];
#pragma unroll
    for (int mi = 0; mi < 4; mi++)
#pragma unroll
        for (int ni = 0; ni < 8; ni++)
#pragma unroll
            for (int i = 0; i < 4; i++) acc[mi][ni][i] = 0.0f;

    const int NKB = K >> 5;
    issue_stage(sb, 0, 0,  Ahb, Alb, Bhb, Blb, lda, ldb, tid);
    issue_stage(sb, 1, 32, Ahb, Alb, Bhb, Blb, lda, ldb, tid);

    for (int kb = 0; kb < NKB; kb++) {
        if (kb < NKB - 2) asm volatile("cp.async.wait_group 1;" ::: "memory");
        else              asm volatile("cp.async.wait_group 0;" ::: "memory");
        __syncthreads();
        if (kb + 2 < NKB)
            issue_stage(sb, (kb + 2) % 3, (kb + 2) * 32,
                        Ahb, Alb, Bhb, Blb, lda, ldb, tid);

        const uint32_t s = sb + (uint32_t)(kb % 3) * STGB;
#pragma unroll
        for (int kk = 0; kk < 2; kk++) {
            const uint32_t aK = kk ? aK1 : aK0;
            const uint32_t bK = kk ? bK1 : bK0;
            uint32_t ah[4][4], al4[4][4];
#pragma unroll
            for (int mi = 0; mi < 4; mi++) {
                ldsm4(ah[mi],  s +       aRow + mi * 1024 + aK);
                ldsm4(al4[mi], s + OPB + aRow + mi * 1024 + aK);
            }
#pragma unroll
            for (int g = 0; g < 4; g++) {
                uint32_t bh[4], bl[4];
                ldsm4(bh, s + 2 * OPB + bRow + g * 1024 + bK);
                ldsm4(bl, s + 3 * OPB + bRow + g * 1024 + bK);
#pragma unroll
                for (int mi = 0; mi < 4; mi++)
#pragma unroll
                    for (int nk = 0; nk < 2; nk++) {
                        float* c = acc[mi][g * 2 + nk];
                        mma_bf16(c, ah[mi],  &bh[nk * 2]);
                        mma_bf16(c, ah[mi],  &bl[nk * 2]);
                        mma_bf16(c, al4[mi], &bh[nk * 2]);
                    }
            }
        }
    }

    const int cr = l >> 2, cc2 = (l & 3) * 2;

    if (OM == 2) {
        // ---- fused RoPE + split epilogue (GEMM1) ----
        __syncthreads();                       // mainloop smem reads done
        float* sE = (float*)smraw;             // 128 x 132 fp32 staging (67.6KB <= 96KB)
#pragma unroll
        for (int ni = 0; ni < 8; ni++) {
            const int colg = nb + wn + ni * 8 + cc2;
            const float b0 = bias[colg], b1 = bias[colg + 1];
            const int colL = wn + ni * 8 + cc2;
#pragma unroll
            for (int mi = 0; mi < 4; mi++) {
                const int rowL = wm + mi * 16 + cr;
                sE[rowL * 132 + colL]           = acc[mi][ni][0] + b0;
                sE[rowL * 132 + colL + 1]       = acc[mi][ni][1] + b1;
                sE[(rowL + 8) * 132 + colL]     = acc[mi][ni][2] + b0;
                sE[(rowL + 8) * 132 + colL + 1] = acc[mi][ni][3] + b1;
            }
        }
        __syncthreads();
        const bool doRope = (blockIdx.x < 16);      // q,k tiles; v tiles pass through
        const int i0 = (tid & 15) << 1;
        const int hh = (tid >> 4) & 1;
        const int rb0 = tid >> 5;                   // 0..3
        const float invA = (float)exp2(-(double)i0 * 0.41524101186091903);
        const float invB = (float)exp2(-(double)(i0 + 1) * 0.41524101186091903);
        const int colL = hh * 64 + i0;
#pragma unroll 4
        for (int rr = 0; rr < 32; rr++) {
            const int row = rb0 + (rr << 2);
            float cA = 1.0f, sA = 0.0f, cB = 1.0f, sB = 0.0f;
            if (doRope) {
                const float sPos = (float)((mb + row) & (S_LEN - 1));
                sincosf(sPos * invA, &sA, &cA);
                sincosf(sPos * invB, &sB, &cB);
            }
            float2 x0 = *(float2*)&sE[row * 132 + colL];
            float2 x1 = *(float2*)&sE[row * 132 + colL + 32];
            float r00 = x0.x * cA - x1.x * sA, r01 = x0.y * cB - x1.y * sB;
            float r10 = x1.x * cA + x0.x * sA, r11 = x1.y * cB + x0.y * sB;
            uint32_t h0, l0, h1, l1;
            split2(r00, r01, h0, l0);
            split2(r10, r11, h1, l1);
            const size_t base = (size_t)(mb + row) * ldc + nb + colL;
            *(uint32_t*)(Ch + base)      = h0;
            *(uint32_t*)(Cl + base)      = l0;
            *(uint32_t*)(Ch + base + 32) = h1;
            *(uint32_t*)(Cl + base + 32) = l1;
        }
        return;
    }

    if (OM == 3) {
        // ---- merged q2/k2/v2 epilogue: route by segment ----
        __nv_bfloat16* Coh = (seg == 0) ? g_qh : (seg == 1) ? g_kh : g_vh;
        __nv_bfloat16* Col = (seg == 0) ? g_ql : (seg == 1) ? g_kl : g_vl;
        const float sc = (seg == 0) ? 0.125f : 1.0f;
        const int nbo = nb - (seg << 10);
#pragma unroll
        for (int ni = 0; ni < 8; ni++) {
            const int colg = nb + wn + ni * 8 + cc2;
            const float b0 = bias[colg], b1 = bias[colg + 1];
            const int col = nbo + wn + ni * 8 + cc2;
#pragma unroll
            for (int mi = 0; mi < 4; mi++) {
                const int row = mb + wm + mi * 16 + cr;
                float v0 = (acc[mi][ni][0] + b0) * sc, v1 = (acc[mi][ni][1] + b1) * sc;
                float v2 = (acc[mi][ni][2] + b0) * sc, v3 = (acc[mi][ni][3] + b1) * sc;
                uint32_t h0, l0, h1, l1;
                split2(v0, v1, h0, l0);
                split2(v2, v3, h1, l1);
                *(uint32_t*)(Coh + (size_t)row * 1024 + col) = h0;
                *(uint32_t*)(Col + (size_t)row * 1024 + col) = l0;
                *(uint32_t*)(Coh + (size_t)(row + 8) * 1024 + col) = h1;
                *(uint32_t*)(Col + (size_t)(row + 8) * 1024 + col) = l1;
            }
        }
        return;
    }

    // OM == 0: fp32 out
#pragma unroll
    for (int ni = 0; ni < 8; ni++) {
        const int col = nb + wn + ni * 8 + cc2;
        const float b0 = bias[col], b1 = bias[col + 1];
#pragma unroll
        for (int mi = 0; mi < 4; mi++) {
            const int row = mb + wm + mi * 16 + cr;
            *(float2*)(C + (size_t)row * ldc + col) =
                make_float2(acc[mi][ni][0] + b0, acc[mi][ni][1] + b1);
            *(float2*)(C + (size_t)(row + 8) * ldc + col) =
                make_float2(acc[mi][ni][2] + b0, acc[mi][ni][3] + b1);
        }
    }
}

// ---------------- Flash attention on mma.sync bf16x2 (R10 proven) ----------------
#define ATT_QL   8192
#define ATT_MASK 16384
#define ATT_KV   18432
#define ATT_STG  32768
#define ATT_SMEM (ATT_KV + 2 * ATT_STG)   // 83968
#define NITER    32

__global__ __launch_bounds__(128, 2)
void attn_mma(const __nv_bfloat16* __restrict__ qh, const __nv_bfloat16* __restrict__ ql,
              const __nv_bfloat16* __restrict__ kh, const __nv_bfloat16* __restrict__ kl,
              const __nv_bfloat16* __restrict__ vh, const __nv_bfloat16* __restrict__ vl,
              const unsigned char* __restrict__ maskg,
              __nv_bfloat16* __restrict__ Oh, __nv_bfloat16* __restrict__ Ol)
{
    extern __shared__ char sm[];
    const uint32_t sb = smem_u32(sm);
    const int tid = threadIdx.x, l = tid & 31, w = tid >> 5;
    const int b = blockIdx.z, h = blockIdx.y, q0 = blockIdx.x << 6;
    const size_t rowbase = (size_t)b * S_LEN;
    const int h64 = h << 6;

    {
        const int tile = tid >> 6;
        const __nv_bfloat16* src = tile ? ql : qh;
        const uint32_t dstb = sb + tile * ATT_QL;
        const int base = tid & 63;
#pragma unroll
        for (int i = 0; i < 8; i++) {
            int idx = base + i * 64; int r = idx >> 3, c = idx & 7;
            cp16(dstb + r * 128 + ((c ^ (r & 7)) << 4),
                 src + (rowbase + q0 + r) * 1024 + h64 + c * 8);
        }
        cp16(sb + ATT_MASK + tid * 16, maskg + (size_t)b * S_LEN + tid * 16);
    }
    const int kvtile = tid >> 5;
    const __nv_bfloat16* kvsrc = (kvtile == 0) ? kh : (kvtile == 1) ? kl : (kvtile == 2) ? vh : vl;
    const int kvbase = tid & 31;
#define LOAD_KV(stg, kb) do {                                                     \
        uint32_t dstb = sb + ATT_KV + (stg) * ATT_STG + kvtile * 8192;            \
        _Pragma("unroll")                                                         \
        for (int i = 0; i < 16; i++) {                                            \
            int idx = kvbase + i * 32; int r = idx >> 3, c = idx & 7;             \
            cp16(dstb + r * 128 + ((c ^ (r & 7)) << 4),                           \
                 kvsrc + (rowbase + (kb) + r) * 1024 + h64 + c * 8);              \
        }                                                                         \
        asm volatile("cp.async.commit_group;" ::: "memory");                      \
    } while (0)

    LOAD_KV(0, 0);
    LOAD_KV(1, 64);

    asm volatile("cp.async.wait_group 1;" ::: "memory");
    __syncthreads();

    uint32_t qfh[4][4], qfl[4][4];
    {
        int row = (w << 4) + (l & 15);
#pragma unroll
        for (int j = 0; j < 4; j++) {
            uint32_t ch = (uint32_t)(((2 * j + (l >> 4)) ^ (row & 7)) << 4);
            ldsm4(qfh[j], sb +          row * 128 + ch);
            ldsm4(qfl[j], sb + ATT_QL + row * 128 + ch);
        }
    }

    float o[8][4];
#pragma unroll
    for (int di = 0; di < 8; di++)
#pragma unroll
        for (int i = 0; i < 4; i++) o[di][i] = 0.0f;
    float m0 = -1e30f, m1 = -1e30f, l0 = 0.0f, l1 = 0.0f;

    const unsigned char* Ms = (const unsigned char*)sm + ATT_MASK;

    for (int kt = 0; kt < NITER; kt++) {
        if (kt > 0) {
            if (kt < 30) asm volatile("cp.async.wait_group 1;" ::: "memory");
            else         asm volatile("cp.async.wait_group 0;" ::: "memory");
            __syncthreads();
        }
        const uint32_t stg = sb + ATT_KV + (uint32_t)(kt & 1) * ATT_STG;
        const int kb = kt << 6;

        float S[8][4];
#pragma unroll
        for (int ni = 0; ni < 8; ni++)
#pragma unroll
            for (int i = 0; i < 4; i++) S[ni][i] = 0.0f;

#pragma unroll
        for (int j = 0; j < 4; j++) {
            uint32_t bh4[4][4], bl4[4][4];
#pragma unroll
            for (int ng = 0; ng < 4; ng++) {
                int row = (ng << 4) + (l & 7) + ((l >> 4) << 3);
                uint32_t ch = (uint32_t)(((2 * j + ((l >> 3) & 1)) ^ (row & 7)) << 4);
                ldsm4(bh4[ng], stg +        row * 128 + ch);
                ldsm4(bl4[ng], stg + 8192 + row * 128 + ch);
            }
#pragma unroll
            for (int ni = 0; ni < 8; ni++) {
                uint32_t* bp = &bh4[ni >> 1][(ni & 1) * 2];
                uint32_t* lp = &bl4[ni >> 1][(ni & 1) * 2];
                mma_bf16(S[ni], qfh[j], bp);
                mma_bf16(S[ni], qfh[j], lp);
                mma_bf16(S[ni], qfl[j], bp);
            }
        }

        float tm0 = -1e30f, tm1 = -1e30f;
#pragma unroll
        for (int ni = 0; ni < 8; ni++) {
            uchar2 mm = *(const uchar2*)(Ms + kb + (ni << 3) + ((l & 3) << 1));
            if (mm.x) { S[ni][0] = -1e30f; S[ni][2] = -1e30f; }
            if (mm.y) { S[ni][1] = -1e30f; S[ni][3] = -1e30f; }
            tm0 = fmaxf(tm0, fmaxf(S[ni][0], S[ni][1]));
            tm1 = fmaxf(tm1, fmaxf(S[ni][2], S[ni][3]));
        }
        tm0 = fmaxf(tm0, __shfl_xor_sync(0xffffffffu, tm0, 1));
        tm0 = fmaxf(tm0, __shfl_xor_sync(0xffffffffu, tm0, 2));
        tm1 = fmaxf(tm1, __shfl_xor_sync(0xffffffffu, tm1, 1));
        tm1 = fmaxf(tm1, __shfl_xor_sync(0xffffffffu, tm1, 2));
        float mn0 = fmaxf(m0, tm0), mn1 = fmaxf(m1, tm1);
        float c0 = __expf(m0 - mn0), c1 = __expf(m1 - mn1);
        m0 = mn0; m1 = mn1;
        float rs0 = 0.0f, rs1 = 0.0f;
#pragma unroll
        for (int ni = 0; ni < 8; ni++) {
            S[ni][0] = __expf(S[ni][0] - mn0); rs0 += S[ni][0];
            S[ni][1] = __expf(S[ni][1] - mn0); rs0 += S[ni][1];
            S[ni][2] = __expf(S[ni][2] - mn1); rs1 += S[ni][2];
            S[ni][3] = __expf(S[ni][3] - mn1); rs1 += S[ni][3];
        }
        rs0 += __shfl_xor_sync(0xffffffffu, rs0, 1);
        rs0 += __shfl_xor_sync(0xffffffffu, rs0, 2);
        rs1 += __shfl_xor_sync(0xffffffffu, rs1, 1);
        rs1 += __shfl_xor_sync(0xffffffffu, rs1, 2);
        l0 = l0 * c0 + rs0; l1 = l1 * c1 + rs1;
#pragma unroll
        for (int di = 0; di < 8; di++) {
            o[di][0] *= c0; o[di][1] *= c0; o[di][2] *= c1; o[di][3] *= c1;
        }

#pragma unroll
        for (int js = 0; js < 4; js++) {
            uint32_t pha[4], pla[4];
            {
                const int t0 = 2 * js, t1 = t0 + 1;
                split2(S[t0][0], S[t0][1], pha[0], pla[0]);
                split2(S[t0][2], S[t0][3], pha[1], pla[1]);
                split2(S[t1][0], S[t1][1], pha[2], pla[2]);
                split2(S[t1][2], S[t1][3], pha[3], pla[3]);
            }
            uint32_t vh4[4][4], vl4[4][4];
#pragma unroll
            for (int dg = 0; dg < 4; dg++) {
                int row = (js << 4) + (l & 7) + (((l >> 3) & 1) << 3);
                uint32_t ch = (uint32_t)(((2 * dg + (l >> 4)) ^ (row & 7)) << 4);
                ldsm4t(vh4[dg], stg + 16384 + row * 128 + ch);
                ldsm4t(vl4[dg], stg + 24576 + row * 128 + ch);
            }
#pragma unroll
            for (int di = 0; di < 8; di++) {
                uint32_t* vp = &vh4[di >> 1][(di & 1) * 2];
                uint32_t* lp = &vl4[di >> 1][(di & 1) * 2];
                mma_bf16(o[di], pha, vp);
                mma_bf16(o[di], pha, lp);
                mma_bf16(o[di], pla, vp);
            }
        }

        __syncthreads();
        if (kt + 2 < NITER) LOAD_KV(kt & 1, (kt + 2) << 6);
    }

    const float inv0 = 1.0f / l0, inv1 = 1.0f / l1;
    const int r0 = q0 + (w << 4) + (l >> 2);
#pragma unroll
    for (int di = 0; di < 8; di++) {
        const int col = h64 + (di << 3) + ((l & 3) << 1);
        uint32_t h0, lo0, h1, lo1;
        split2(o[di][0] * inv0, o[di][1] * inv0, h0, lo0);
        split2(o[di][2] * inv1, o[di][3] * inv1, h1, lo1);
        *(uint32_t*)(Oh + (rowbase + r0) * 1024 + col) = h0;
        *(uint32_t*)(Ol + (rowbase + r0) * 1024 + col) = lo0;
        *(uint32_t*)(Oh + (rowbase + r0 + 8) * 1024 + col) = h1;
        *(uint32_t*)(Ol + (rowbase + r0 + 8) * 1024 + col) = lo1;
    }
}

// ---------------- launch ----------------
extern "C" void kernel_launch(void* const* d_in, const int* in_sizes, int n_in,
                              void* d_out, int out_size)
{
    const float* x     = (const float*)d_in[0];
    const float* w_in  = (const float*)d_in[1];
    const float* b_in  = (const float*)d_in[2];
    const float* w_out = (const float*)d_in[3];
    const float* b_out = (const float*)d_in[4];
    const unsigned char* mask = (const unsigned char*)d_in[5];
    float* out = (float*)d_out;

    __nv_bfloat16 *xh, *xl, *wih, *wil, *woh, *wol, *qkh, *qkl;
    __nv_bfloat16 *qh, *ql, *kh, *kl, *vh, *vl, *cth, *ctl;
    cudaGetSymbolAddress((void**)&xh,  g_xh);  cudaGetSymbolAddress((void**)&xl,  g_xl);
    cudaGetSymbolAddress((void**)&wih, g_wih); cudaGetSymbolAddress((void**)&wil, g_wil);
    cudaGetSymbolAddress((void**)&woh, g_woh); cudaGetSymbolAddress((void**)&wol, g_wol);
    cudaGetSymbolAddress((void**)&qkh, g_qkh); cudaGetSymbolAddress((void**)&qkl, g_qkl);
    cudaGetSymbolAddress((void**)&qh,  g_qh);  cudaGetSymbolAddress((void**)&ql,  g_ql);
    cudaGetSymbolAddress((void**)&kh,  g_kh);  cudaGetSymbolAddress((void**)&kl,  g_kl);
    cudaGetSymbolAddress((void**)&vh,  g_vh);  cudaGetSymbolAddress((void**)&vl,  g_vl);
    cudaGetSymbolAddress((void**)&cth, g_cth); cudaGetSymbolAddress((void**)&ctl, g_ctl);

    cudaFuncSetAttribute(gemm_mma<0>, cudaFuncAttributeMaxDynamicSharedMemorySize, GEMM_SMEM);
    cudaFuncSetAttribute(gemm_mma<2>, cudaFuncAttributeMaxDynamicSharedMemorySize, GEMM_SMEM);
    cudaFuncSetAttribute(gemm_mma<3>, cudaFuncAttributeMaxDynamicSharedMemorySize, GEMM_SMEM);
    cudaFuncSetAttribute(attn_mma,    cudaFuncAttributeMaxDynamicSharedMemorySize, ATT_SMEM);

    // split inputs
    split_kernel<<<8192, 256>>>(x,     xh,  xl,  2097152);
    split_kernel<<<3072, 256>>>(w_in,  wih, wil, 786432);
    split_kernel<<<1024, 256>>>(w_out, woh, wol, 262144);

    // 1) qkv = x @ Win^T + b with fused RoPE + split -> qkh/qkl (8192 x 3072 bf16)
    gemm_mma<2><<<dim3(24, 64), 128, GEMM_SMEM>>>(xh, xl, 1024, wih, wil, 1024,
                                                  b_in, nullptr, qkh, qkl, 1.0f, 3072, 1024);
    // 2) merged second projection: one launch, outputs routed to qh/ql, kh/kl, vh/vl
    gemm_mma<3><<<dim3(24, 64), 128, GEMM_SMEM>>>(qkh, qkl, 3072, wih, wil, 1024,
                                                  b_in, nullptr, nullptr, nullptr, 1.0f, 1024, 1024);
    // 3) attention (2 CTAs/SM) -> ctx hi/lo
    attn_mma<<<dim3(32, 16, 4), 128, ATT_SMEM>>>(qh, ql, kh, kl, vh, vl, mask, cth, ctl);
    // 4) out = ctx @ Wout^T + b (fp32 out)
    gemm_mma<0><<<dim3(8, 64), 128, GEMM_SMEM>>>(cth, ctl, 1024, woh, wol, 1024,
                                                 b_out, out, nullptr, nullptr, 1.0f, 1024, 1024);
}